// round 6
// baseline (speedup 1.0000x reference)
#include <cuda_runtime.h>
#include <cstdint>

using u64 = unsigned long long;

#define T_STEPS 50
#define BATCH 32768
#define BLOCK 64
#define GRID (BATCH / BLOCK)      // 512 blocks, 1 thread = 1 trajectory

#define DT_F 0.01f
#define GAMMA_F 0.1f
#define SIGMA_F 0.2f
#define LC_SCALE (0.5f * 0.01f * 0.25f)   // 0.5*DT*TAU^2

// ---------------------------------------------------------------------------
// f32x2 helpers: u64 = packed (lo,hi) floats.  State stays scalar; only GEMV
// accumulators are packed (across adjacent output / inner indices).
// ---------------------------------------------------------------------------
__device__ __forceinline__ u64 dup2(float x) {
    u64 r; asm("mov.b64 %0, {%1, %1};" : "=l"(r) : "f"(x)); return r;
}
__device__ __forceinline__ u64 pk2(float a, float b) {
    u64 r; asm("mov.b64 %0, {%1, %2};" : "=l"(r) : "f"(a), "f"(b)); return r;
}
__device__ __forceinline__ void upk(float& lo, float& hi, u64 v) {
    asm("mov.b64 {%0, %1}, %2;" : "=f"(lo), "=f"(hi) : "l"(v));
}
__device__ __forceinline__ u64 f2fma(u64 a, u64 b, u64 c) {
    u64 d; asm("fma.rn.f32x2 %0, %1, %2, %3;" : "=l"(d) : "l"(a), "l"(b), "l"(c)); return d;
}

// ---------------------------------------------------------------------------
// shared weights: plain floats, every array has an even float count so all
// row starts are 8B-aligned (u64 pair loads are legal everywhere).
// ---------------------------------------------------------------------------
struct __align__(16) SW {
    float A[16][16]; float C[16][16]; float B[16][8]; float D[16][8];
    float pW1[17][10]; float pb1[10]; float pW2[10][10]; float pb2[10];
    float pW3[10][8];  float pb3[8];
    float zW1[17][10]; float zb1[10]; float zW2[10][10]; float zb2[10];
    float zW3[10][16]; float zb3[16];
    float yW1[16][10]; float yb1[10]; float yW2[10][10]; float yb2[10];
    float yW3[10][16]; float yb3[16];
};

__device__ float g_p0[GRID];
__device__ float g_p1[GRID];

__device__ __forceinline__ void cp(float* dst, const float* src, int n) {
    for (int k = threadIdx.x; k < n; k += blockDim.x) dst[k] = src[k];
}

__device__ __forceinline__ float tanh_fast(float x) {
    float ax = fabsf(x);
    float e  = __expf(-2.0f * ax);
    float r  = __fdividef(1.0f - e, 1.0f + e);
    return copysignf(r, x);
}
__device__ __forceinline__ void th10(float* h) {
#pragma unroll
    for (int j = 0; j < 10; j++) h[j] = tanh_fast(h[j]);
}

// out[j] = bias[j] + sum_i x[i]*W[i][j]   (packed over j)
template <int NIN, int NOUT>
__device__ __forceinline__ void gemv_p(float* out, const float* x,
                                       const float* W, const float* bias) {
    u64 acc[NOUT / 2];
    const u64* bp = reinterpret_cast<const u64*>(bias);
#pragma unroll
    for (int j = 0; j < NOUT / 2; j++) acc[j] = bp[j];
#pragma unroll
    for (int i = 0; i < NIN; i++) {
        u64 xi = dup2(x[i]);
        const u64* wr = reinterpret_cast<const u64*>(W + i * NOUT);
#pragma unroll
        for (int j = 0; j < NOUT / 2; j++) acc[j] = f2fma(xi, wr[j], acc[j]);
    }
#pragma unroll
    for (int j = 0; j < NOUT / 2; j++) upk(out[2 * j], out[2 * j + 1], acc[j]);
}

// hidden1 of the [t, X] nets: out = bias + t*W[0][:] + sum_i X[i]*W[1+i][:]
template <int NOUT>
__device__ __forceinline__ void gemv_tx(float* out, float tt, const float* X,
                                        const float* W17, const float* bias) {
    u64 acc[NOUT / 2];
    const u64* bp = reinterpret_cast<const u64*>(bias);
#pragma unroll
    for (int j = 0; j < NOUT / 2; j++) acc[j] = bp[j];
    {
        u64 ti = dup2(tt);
        const u64* wr = reinterpret_cast<const u64*>(W17);
#pragma unroll
        for (int j = 0; j < NOUT / 2; j++) acc[j] = f2fma(ti, wr[j], acc[j]);
    }
#pragma unroll
    for (int i = 0; i < 16; i++) {
        u64 xi = dup2(X[i]);
        const u64* wr = reinterpret_cast<const u64*>(W17 + (i + 1) * NOUT);
#pragma unroll
        for (int j = 0; j < NOUT / 2; j++) acc[j] = f2fma(xi, wr[j], acc[j]);
    }
#pragma unroll
    for (int j = 0; j < NOUT / 2; j++) upk(out[2 * j], out[2 * j + 1], acc[j]);
}

// acc[j] += sum_i x[i]*W[i][j]   (acc packed, NOUT even)
template <int NIN, int NOUT>
__device__ __forceinline__ void gemv_add(u64* acc, const float* x, const float* W) {
#pragma unroll
    for (int i = 0; i < NIN; i++) {
        u64 xi = dup2(x[i]);
        const u64* wr = reinterpret_cast<const u64*>(W + i * NOUT);
#pragma unroll
        for (int j = 0; j < NOUT / 2; j++) acc[j] = f2fma(xi, wr[j], acc[j]);
    }
}

// ---------------------------------------------------------------------------
// main simulation: one thread == one trajectory
// ---------------------------------------------------------------------------
__global__ void __launch_bounds__(BLOCK) sim_kernel(
    const float* __restrict__ dw, const float* __restrict__ X0,
    const float* __restrict__ A,  const float* __restrict__ Bm,
    const float* __restrict__ Cm, const float* __restrict__ Dm,
    const float* __restrict__ pW1, const float* __restrict__ pb1,
    const float* __restrict__ pW2, const float* __restrict__ pb2,
    const float* __restrict__ pW3, const float* __restrict__ pb3,
    const float* __restrict__ zW1, const float* __restrict__ zb1,
    const float* __restrict__ zW2, const float* __restrict__ zb2,
    const float* __restrict__ zW3, const float* __restrict__ zb3,
    const float* __restrict__ yW1, const float* __restrict__ yb1,
    const float* __restrict__ yW2, const float* __restrict__ yb2,
    const float* __restrict__ yW3, const float* __restrict__ yb3)
{
    __shared__ SW s;

    cp(&s.A[0][0], A, 256);  cp(&s.C[0][0], Cm, 256);
    cp(&s.B[0][0], Bm, 128); cp(&s.D[0][0], Dm, 128);
    cp(&s.pW1[0][0], pW1, 170); cp(s.pb1, pb1, 10);
    cp(&s.pW2[0][0], pW2, 100); cp(s.pb2, pb2, 10);
    cp(&s.pW3[0][0], pW3, 80);  cp(s.pb3, pb3, 8);
    cp(&s.zW1[0][0], zW1, 170); cp(s.zb1, zb1, 10);
    cp(&s.zW2[0][0], zW2, 100); cp(s.zb2, zb2, 10);
    cp(&s.zW3[0][0], zW3, 160); cp(s.zb3, zb3, 16);
    cp(&s.yW1[0][0], yW1, 160); cp(s.yb1, yb1, 10);
    cp(&s.yW2[0][0], yW2, 100); cp(s.yb2, yb2, 10);
    cp(&s.yW3[0][0], yW3, 160); cp(s.yb3, yb3, 16);
    __syncthreads();

    const int b = blockIdx.x * BLOCK + threadIdx.x;

    float X[16], Y[16];
#pragma unroll
    for (int j = 0; j < 4; j++) {
        float4 v = reinterpret_cast<const float4*>(X0 + (size_t)b * 16)[j];
        X[4 * j + 0] = v.x; X[4 * j + 1] = v.y;
        X[4 * j + 2] = v.z; X[4 * j + 3] = v.w;
    }

    // ---- Y = MLP_Y0(X0) ----
    {
        float h1[10], h2[10];
        gemv_p<16, 10>(h1, X, &s.yW1[0][0], s.yb1);  th10(h1);
        gemv_p<10, 10>(h2, h1, &s.yW2[0][0], s.yb2); th10(h2);
        gemv_p<10, 16>(Y, h2, &s.yW3[0][0], s.yb3);
    }

    float lc = 0.0f;
    const float* dwp = dw + b;

    for (int t = 0; t < T_STEPS; t++) {
        float tt = (float)t * DT_F;

        // ---- Zv = MLP_Z([t, X]) ----
        float Zv[16];
        {
            float h1[10], h2[10];
            gemv_tx<10>(h1, tt, X, &s.zW1[0][0], s.zb1); th10(h1);
            gemv_p<10, 10>(h2, h1, &s.zW2[0][0], s.zb2); th10(h2);
            gemv_p<10, 16>(Zv, h2, &s.zW3[0][0], s.zb3);
        }

        // ---- u = MLP_phi([t, X]) ----
        float u[8];
        {
            float h1[10], h2[10];
            gemv_tx<10>(h1, tt, X, &s.pW1[0][0], s.pb1); th10(h1);
            gemv_p<10, 10>(h2, h1, &s.pW2[0][0], s.pb2); th10(h2);
            gemv_p<10, 8>(u, h2, &s.pW3[0][0], s.pb3);
        }

        float dwi = __ldg(dwp + (size_t)t * BATCH);

        // ---- dH = u + Y@B + Zv@D  ->  lc ----
        {
            u64 acc[4];
#pragma unroll
            for (int j = 0; j < 4; j++) acc[j] = pk2(u[2 * j], u[2 * j + 1]);
            gemv_add<16, 8>(acc, Y, &s.B[0][0]);
            gemv_add<16, 8>(acc, Zv, &s.D[0][0]);
            u64 ssp = f2fma(acc[0], acc[0], 0ull);
#pragma unroll
            for (int j = 1; j < 4; j++) ssp = f2fma(acc[j], acc[j], ssp);
            float slo, shi; upk(slo, shi, ssp);
            float w = (t == 0 || t == T_STEPS - 1) ? LC_SCALE : 2.0f * LC_SCALE;
            lc = fmaf(w, slo + shi, lc);
        }

        // ---- Y update: Y += -DT*(Y@A + Zv@C + X) + dwi*Zv ----
        {
            u64 acc[8];
#pragma unroll
            for (int j = 0; j < 8; j++) acc[j] = pk2(X[2 * j], X[2 * j + 1]);
            gemv_add<16, 16>(acc, Y, &s.A[0][0]);
            gemv_add<16, 16>(acc, Zv, &s.C[0][0]);
#pragma unroll
            for (int j = 0; j < 8; j++) {
                float lo, hi; upk(lo, hi, acc[j]);
                Y[2 * j]     = fmaf(dwi, Zv[2 * j],     fmaf(lo, -DT_F, Y[2 * j]));
                Y[2 * j + 1] = fmaf(dwi, Zv[2 * j + 1], fmaf(hi, -DT_F, Y[2 * j + 1]));
            }
        }

        // ---- X update: X += DT*(X@A^T + u@B^T + GAMMA) + dwi*(X@C^T + u@D^T + SIGMA)
        {
            u64 xp[8], up[4];
#pragma unroll
            for (int j = 0; j < 8; j++) xp[j] = pk2(X[2 * j], X[2 * j + 1]);
#pragma unroll
            for (int j = 0; j < 4; j++) up[j] = pk2(u[2 * j], u[2 * j + 1]);

            float Xn[16];
#pragma unroll
            for (int i = 0; i < 16; i++) {
                const u64* ar = reinterpret_cast<const u64*>(&s.A[i][0]);
                const u64* br = reinterpret_cast<const u64*>(&s.B[i][0]);
                const u64* cr = reinterpret_cast<const u64*>(&s.C[i][0]);
                const u64* dr = reinterpret_cast<const u64*>(&s.D[i][0]);
                u64 sd = f2fma(xp[0], ar[0], 0ull);
                u64 sf = f2fma(xp[0], cr[0], 0ull);
#pragma unroll
                for (int j = 1; j < 8; j++) {
                    sd = f2fma(xp[j], ar[j], sd);
                    sf = f2fma(xp[j], cr[j], sf);
                }
#pragma unroll
                for (int j = 0; j < 4; j++) {
                    sd = f2fma(up[j], br[j], sd);
                    sf = f2fma(up[j], dr[j], sf);
                }
                float dlo, dhi, flo, fhi;
                upk(dlo, dhi, sd); upk(flo, fhi, sf);
                float drift = GAMMA_F + dlo + dhi;
                float diff  = SIGMA_F + flo + fhi;
                Xn[i] = fmaf(dwi, diff, fmaf(drift, DT_F, X[i]));
            }
#pragma unroll
            for (int i = 0; i < 16; i++) X[i] = Xn[i];
        }
    }

    float lb = 0.0f;
#pragma unroll
    for (int i = 0; i < 16; i++) {
        float d = Y[i] - X[i];
        lb = fmaf(d, d, lb);
    }

    // ---- block reduction (64 threads = 2 warps) ----
#pragma unroll
    for (int o = 16; o; o >>= 1) {
        lb += __shfl_down_sync(0xffffffffu, lb, o);
        lc += __shfl_down_sync(0xffffffffu, lc, o);
    }
    __shared__ float r0[2], r1[2];
    int warp = threadIdx.x >> 5, lane = threadIdx.x & 31;
    if (lane == 0) { r0[warp] = lb; r1[warp] = lc; }
    __syncthreads();
    if (threadIdx.x == 0) {
        g_p0[blockIdx.x] = r0[0] + r0[1];
        g_p1[blockIdx.x] = r1[0] + r1[1];
    }
}

// ---------------------------------------------------------------------------
// final reduction: GRID partials -> 2 means
// ---------------------------------------------------------------------------
__global__ void __launch_bounds__(GRID) finalize_kernel(float* __restrict__ out) {
    int tid = threadIdx.x;
    float a = g_p0[tid];
    float c = g_p1[tid];
#pragma unroll
    for (int o = 16; o; o >>= 1) {
        a += __shfl_down_sync(0xffffffffu, a, o);
        c += __shfl_down_sync(0xffffffffu, c, o);
    }
    __shared__ float sa[GRID / 32], sc[GRID / 32];
    int warp = tid >> 5, lane = tid & 31;
    if (lane == 0) { sa[warp] = a; sc[warp] = c; }
    __syncthreads();
    if (warp == 0) {
        a = (lane < GRID / 32) ? sa[lane] : 0.0f;
        c = (lane < GRID / 32) ? sc[lane] : 0.0f;
#pragma unroll
        for (int o = 8; o; o >>= 1) {
            a += __shfl_down_sync(0xffffffffu, a, o);
            c += __shfl_down_sync(0xffffffffu, c, o);
        }
        if (lane == 0) {
            out[0] = a * (1.0f / (float)BATCH);
            out[1] = c * (1.0f / (float)BATCH);
        }
    }
}

extern "C" void kernel_launch(void* const* d_in, const int* in_sizes, int n_in,
                              void* d_out, int out_size) {
    const float* dw  = (const float*)d_in[0];
    const float* X0  = (const float*)d_in[1];
    const float* A   = (const float*)d_in[2];
    const float* Bm  = (const float*)d_in[3];
    const float* Cm  = (const float*)d_in[4];
    const float* Dm  = (const float*)d_in[5];
    const float* pW1 = (const float*)d_in[6];
    const float* pb1 = (const float*)d_in[7];
    const float* pW2 = (const float*)d_in[8];
    const float* pb2 = (const float*)d_in[9];
    const float* pW3 = (const float*)d_in[10];
    const float* pb3 = (const float*)d_in[11];
    const float* zW1 = (const float*)d_in[12];
    const float* zb1 = (const float*)d_in[13];
    const float* zW2 = (const float*)d_in[14];
    const float* zb2 = (const float*)d_in[15];
    const float* zW3 = (const float*)d_in[16];
    const float* zb3 = (const float*)d_in[17];
    const float* yW1 = (const float*)d_in[18];
    const float* yb1 = (const float*)d_in[19];
    const float* yW2 = (const float*)d_in[20];
    const float* yb2 = (const float*)d_in[21];
    const float* yW3 = (const float*)d_in[22];
    const float* yb3 = (const float*)d_in[23];

    sim_kernel<<<GRID, BLOCK>>>(dw, X0, A, Bm, Cm, Dm,
                                pW1, pb1, pW2, pb2, pW3, pb3,
                                zW1, zb1, zW2, zb2, zW3, zb3,
                                yW1, yb1, yW2, yb2, yW3, yb3);
    finalize_kernel<<<1, GRID>>>((float*)d_out);
}

// round 7
// speedup vs baseline: 1.1889x; 1.1889x over previous
#include <cuda_runtime.h>
#include <cstdint>

#define T_STEPS 50
#define HP 12            // hidden width padded 10 -> 12 (zero-padded weights)
#define BATCH 32768
#define BLOCK 128
#define GRID (BATCH / BLOCK)    // 256 blocks, 4 warps each -> uniform SMSP coverage

#define DT_F 0.01f
#define GAMMA_F 0.1f
#define SIGMA_F 0.2f
#define LC_SCALE (0.5f * 0.01f * 0.25f)   // 0.5*DT*TAU^2

// ---------------------------------------------------------------------------
// shared weights, float4-aligned rows (HP=12 pad on hidden dims)
// ---------------------------------------------------------------------------
struct __align__(16) SW {
    float A[16][16];
    float C[16][16];
    float B[16][8];
    float D[16][8];

    float pW1[17][HP]; float pb1[HP];
    float pW2[HP][HP]; float pb2[HP];
    float pW3[HP][8];  float pb3[8];

    float zW1[17][HP]; float zb1[HP];
    float zW2[HP][HP]; float zb2[HP];
    float zW3[HP][16]; float zb3[16];

    float yW1[16][HP]; float yb1[HP];
    float yW2[HP][HP]; float yb2[HP];
    float yW3[HP][16]; float yb3[16];
};

__device__ float g_p0[GRID];
__device__ float g_p1[GRID];

// ---------------------------------------------------------------------------
// helpers
// ---------------------------------------------------------------------------
__device__ __forceinline__ float tanh_hw(float x) {
    float r;
    asm("tanh.approx.f32 %0, %1;" : "=f"(r) : "f"(x));
    return r;
}

__device__ __forceinline__ void tanh10(float* h) {
#pragma unroll
    for (int j = 0; j < 10; j++) h[j] = tanh_hw(h[j]);
    h[10] = 0.0f; h[11] = 0.0f;
}

template <int PC>
__device__ __forceinline__ void bias_init(float* acc, const float* b) {
#pragma unroll
    for (int j = 0; j < PC / 4; j++) {
        float4 v = reinterpret_cast<const float4*>(b)[j];
        acc[4 * j + 0] = v.x; acc[4 * j + 1] = v.y;
        acc[4 * j + 2] = v.z; acc[4 * j + 3] = v.w;
    }
}

// acc[j] += sum_i x[i] * W[i][j]  (W row-major, row stride NOUT, NOUT%4==0)
template <int NIN, int NOUT>
__device__ __forceinline__ void gemv_acc(float* acc, const float* x, const float* W) {
#pragma unroll
    for (int i = 0; i < NIN; i++) {
        float xi = x[i];
#pragma unroll
        for (int j = 0; j < NOUT / 4; j++) {
            float4 w = reinterpret_cast<const float4*>(W + i * NOUT)[j];
            acc[4 * j + 0] = fmaf(xi, w.x, acc[4 * j + 0]);
            acc[4 * j + 1] = fmaf(xi, w.y, acc[4 * j + 1]);
            acc[4 * j + 2] = fmaf(xi, w.z, acc[4 * j + 2]);
            acc[4 * j + 3] = fmaf(xi, w.w, acc[4 * j + 3]);
        }
    }
}

// acc[i] += dot(x, W[i][:])   (W row-major [NOUT][NIN], NIN%4==0)
template <int NIN, int NOUT>
__device__ __forceinline__ void dotrows_acc(float* acc, const float* x, const float* W) {
#pragma unroll
    for (int i = 0; i < NOUT; i++) {
        float s = acc[i];
#pragma unroll
        for (int j = 0; j < NIN / 4; j++) {
            float4 w = reinterpret_cast<const float4*>(W + i * NIN)[j];
            s = fmaf(x[4 * j + 0], w.x, s);
            s = fmaf(x[4 * j + 1], w.y, s);
            s = fmaf(x[4 * j + 2], w.z, s);
            s = fmaf(x[4 * j + 3], w.w, s);
        }
        acc[i] = s;
    }
}

__device__ __forceinline__ void copy_pad(float* dst, const float* src,
                                         int rows, int cols, int pcols) {
    int tot = rows * pcols;
    for (int k = threadIdx.x; k < tot; k += blockDim.x) {
        int r = k / pcols;
        int c = k - r * pcols;
        dst[k] = (c < cols) ? src[r * cols + c] : 0.0f;
    }
}

// ---------------------------------------------------------------------------
// main simulation kernel: one thread == one trajectory
// ---------------------------------------------------------------------------
__global__ void __launch_bounds__(BLOCK) sim_kernel(
    const float* __restrict__ dw, const float* __restrict__ X0,
    const float* __restrict__ A,  const float* __restrict__ Bm,
    const float* __restrict__ Cm, const float* __restrict__ Dm,
    const float* __restrict__ pW1, const float* __restrict__ pb1,
    const float* __restrict__ pW2, const float* __restrict__ pb2,
    const float* __restrict__ pW3, const float* __restrict__ pb3,
    const float* __restrict__ zW1, const float* __restrict__ zb1,
    const float* __restrict__ zW2, const float* __restrict__ zb2,
    const float* __restrict__ zW3, const float* __restrict__ zb3,
    const float* __restrict__ yW1, const float* __restrict__ yb1,
    const float* __restrict__ yW2, const float* __restrict__ yb2,
    const float* __restrict__ yW3, const float* __restrict__ yb3)
{
    __shared__ SW s;

    copy_pad(&s.A[0][0],  A,  16, 16, 16);
    copy_pad(&s.C[0][0],  Cm, 16, 16, 16);
    copy_pad(&s.B[0][0],  Bm, 16, 8, 8);
    copy_pad(&s.D[0][0],  Dm, 16, 8, 8);

    copy_pad(&s.pW1[0][0], pW1, 17, 10, HP);
    copy_pad(s.pb1,        pb1, 1, 10, HP);
    copy_pad(&s.pW2[0][0], pW2, 10, 10, HP);
    copy_pad(s.pb2,        pb2, 1, 10, HP);
    copy_pad(&s.pW3[0][0], pW3, 10, 8, 8);
    copy_pad(s.pb3,        pb3, 1, 8, 8);

    copy_pad(&s.zW1[0][0], zW1, 17, 10, HP);
    copy_pad(s.zb1,        zb1, 1, 10, HP);
    copy_pad(&s.zW2[0][0], zW2, 10, 10, HP);
    copy_pad(s.zb2,        zb2, 1, 10, HP);
    copy_pad(&s.zW3[0][0], zW3, 10, 16, 16);
    copy_pad(s.zb3,        zb3, 1, 16, 16);

    copy_pad(&s.yW1[0][0], yW1, 16, 10, HP);
    copy_pad(s.yb1,        yb1, 1, 10, HP);
    copy_pad(&s.yW2[0][0], yW2, 10, 10, HP);
    copy_pad(s.yb2,        yb2, 1, 10, HP);
    copy_pad(&s.yW3[0][0], yW3, 10, 16, 16);
    copy_pad(s.yb3,        yb3, 1, 16, 16);

    __syncthreads();

    const int b = blockIdx.x * BLOCK + threadIdx.x;

    float X[16], Y[16];
#pragma unroll
    for (int j = 0; j < 4; j++) {
        float4 v = reinterpret_cast<const float4*>(X0 + (size_t)b * 16)[j];
        X[4 * j + 0] = v.x; X[4 * j + 1] = v.y;
        X[4 * j + 2] = v.z; X[4 * j + 3] = v.w;
    }

    // ---- Y = MLP_Y0(X0) ----
    {
        float h1[HP];
        bias_init<HP>(h1, s.yb1);
        gemv_acc<16, HP>(h1, X, &s.yW1[0][0]);
        tanh10(h1);
        float h2[HP];
        bias_init<HP>(h2, s.yb2);
        gemv_acc<10, HP>(h2, h1, &s.yW2[0][0]);
        tanh10(h2);
        bias_init<16>(Y, s.yb3);
        gemv_acc<10, 16>(Y, h2, &s.yW3[0][0]);
    }

    float lc = 0.0f;
    const float* dwp = dw + b;

    for (int t = 0; t < T_STEPS; t++) {
        float tt = (float)t * DT_F;
        float dwi = __ldg(dwp + (size_t)t * BATCH);

        // ---- Zv = MLP_Z([t,X]) and u = MLP_phi([t,X]) interleaved for ILP ----
        float Zv[16], u[8];
        {
            float hz[HP], hp[HP];
            bias_init<HP>(hz, s.zb1);
            bias_init<HP>(hp, s.pb1);
            gemv_acc<1, HP>(hz, &tt, &s.zW1[0][0]);
            gemv_acc<1, HP>(hp, &tt, &s.pW1[0][0]);
            gemv_acc<16, HP>(hz, X, &s.zW1[1][0]);
            gemv_acc<16, HP>(hp, X, &s.pW1[1][0]);
            tanh10(hz);
            tanh10(hp);
            float gz[HP], gp[HP];
            bias_init<HP>(gz, s.zb2);
            bias_init<HP>(gp, s.pb2);
            gemv_acc<10, HP>(gz, hz, &s.zW2[0][0]);
            gemv_acc<10, HP>(gp, hp, &s.pW2[0][0]);
            tanh10(gz);
            tanh10(gp);
            bias_init<16>(Zv, s.zb3);
            bias_init<8>(u, s.pb3);
            gemv_acc<10, 16>(Zv, gz, &s.zW3[0][0]);
            gemv_acc<10, 8>(u, gp, &s.pW3[0][0]);
        }

        // ---- dH = u + Y@B + Zv@D -> lc ----
        {
            float dH[8];
#pragma unroll
            for (int m = 0; m < 8; m++) dH[m] = u[m];
            gemv_acc<16, 8>(dH, Y, &s.B[0][0]);
            gemv_acc<16, 8>(dH, Zv, &s.D[0][0]);
            float ss = 0.0f;
#pragma unroll
            for (int m = 0; m < 8; m++) ss = fmaf(dH[m], dH[m], ss);
            float w = (t == 0 || t == T_STEPS - 1) ? LC_SCALE : 2.0f * LC_SCALE;
            lc = fmaf(w, ss, lc);
        }

        // ---- drifts / diffusions ----
        float dX[16], fX[16], dY[16];
#pragma unroll
        for (int i = 0; i < 16; i++) { dX[i] = GAMMA_F; fX[i] = SIGMA_F; dY[i] = X[i]; }

        dotrows_acc<16, 16>(dX, X, &s.A[0][0]);   // X @ A^T
        dotrows_acc<8, 16>(dX, u, &s.B[0][0]);    // u @ B^T
        dotrows_acc<16, 16>(fX, X, &s.C[0][0]);   // X @ C^T
        dotrows_acc<8, 16>(fX, u, &s.D[0][0]);    // u @ D^T

        gemv_acc<16, 16>(dY, Y, &s.A[0][0]);      // Y @ A
        gemv_acc<16, 16>(dY, Zv, &s.C[0][0]);     // Zv @ C

#pragma unroll
        for (int i = 0; i < 16; i++)
            X[i] = fmaf(dwi, fX[i], fmaf(dX[i], DT_F, X[i]));
#pragma unroll
        for (int i = 0; i < 16; i++)
            Y[i] = fmaf(dwi, Zv[i], fmaf(-dY[i], DT_F, Y[i]));
    }

    float lb = 0.0f;
#pragma unroll
    for (int i = 0; i < 16; i++) {
        float d = Y[i] - X[i];
        lb = fmaf(d, d, lb);
    }

    // ---- block reduction (128 threads = 4 warps) ----
#pragma unroll
    for (int o = 16; o; o >>= 1) {
        lb += __shfl_down_sync(0xffffffffu, lb, o);
        lc += __shfl_down_sync(0xffffffffu, lc, o);
    }
    __shared__ float r0[4], r1[4];
    int warp = threadIdx.x >> 5, lane = threadIdx.x & 31;
    if (lane == 0) { r0[warp] = lb; r1[warp] = lc; }
    __syncthreads();
    if (threadIdx.x == 0) {
        g_p0[blockIdx.x] = (r0[0] + r0[1]) + (r0[2] + r0[3]);
        g_p1[blockIdx.x] = (r1[0] + r1[1]) + (r1[2] + r1[3]);
    }
}

// ---------------------------------------------------------------------------
// final reduction: GRID (=256) partials -> 2 means
// ---------------------------------------------------------------------------
__global__ void __launch_bounds__(GRID) finalize_kernel(float* __restrict__ out) {
    int tid = threadIdx.x;
    float a = g_p0[tid];
    float c = g_p1[tid];
#pragma unroll
    for (int o = 16; o; o >>= 1) {
        a += __shfl_down_sync(0xffffffffu, a, o);
        c += __shfl_down_sync(0xffffffffu, c, o);
    }
    __shared__ float sa[GRID / 32], sc[GRID / 32];
    int warp = tid >> 5, lane = tid & 31;
    if (lane == 0) { sa[warp] = a; sc[warp] = c; }
    __syncthreads();
    if (warp == 0) {
        a = (lane < GRID / 32) ? sa[lane] : 0.0f;
        c = (lane < GRID / 32) ? sc[lane] : 0.0f;
#pragma unroll
        for (int o = 4; o; o >>= 1) {
            a += __shfl_down_sync(0xffffffffu, a, o);
            c += __shfl_down_sync(0xffffffffu, c, o);
        }
        if (lane == 0) {
            out[0] = a * (1.0f / (float)BATCH);
            out[1] = c * (1.0f / (float)BATCH);
        }
    }
}

extern "C" void kernel_launch(void* const* d_in, const int* in_sizes, int n_in,
                              void* d_out, int out_size) {
    const float* dw  = (const float*)d_in[0];
    const float* X0  = (const float*)d_in[1];
    const float* A   = (const float*)d_in[2];
    const float* Bm  = (const float*)d_in[3];
    const float* Cm  = (const float*)d_in[4];
    const float* Dm  = (const float*)d_in[5];
    const float* pW1 = (const float*)d_in[6];
    const float* pb1 = (const float*)d_in[7];
    const float* pW2 = (const float*)d_in[8];
    const float* pb2 = (const float*)d_in[9];
    const float* pW3 = (const float*)d_in[10];
    const float* pb3 = (const float*)d_in[11];
    const float* zW1 = (const float*)d_in[12];
    const float* zb1 = (const float*)d_in[13];
    const float* zW2 = (const float*)d_in[14];
    const float* zb2 = (const float*)d_in[15];
    const float* zW3 = (const float*)d_in[16];
    const float* zb3 = (const float*)d_in[17];
    const float* yW1 = (const float*)d_in[18];
    const float* yb1 = (const float*)d_in[19];
    const float* yW2 = (const float*)d_in[20];
    const float* yb2 = (const float*)d_in[21];
    const float* yW3 = (const float*)d_in[22];
    const float* yb3 = (const float*)d_in[23];

    sim_kernel<<<GRID, BLOCK>>>(dw, X0, A, Bm, Cm, Dm,
                                pW1, pb1, pW2, pb2, pW3, pb3,
                                zW1, zb1, zW2, zb2, zW3, zb3,
                                yW1, yb1, yW2, yb2, yW3, yb3);
    finalize_kernel<<<1, GRID>>>((float*)d_out);
}

// round 12
// speedup vs baseline: 1.4079x; 1.1842x over previous
#include <cuda_runtime.h>
#include <cuda_bf16.h>
#include <cstdint>

using u32 = unsigned int;

#define T_STEPS 50
#define BATCH 32768
#define CTA_THREADS 128
#define NCTA (BATCH / CTA_THREADS)   // 256

#define DT_F 0.01f
#define GAMMA_F 0.1f
#define SIGMA_F 0.2f
#define LC_SCALE (0.5f * 0.01f * 0.25f)   // 0.5*DT*TAU^2

#define AST 17   // act row stride (u32 = bf16x2 pairs), odd -> conflict-free writes
#define OST 26   // out row stride (floats), fits N<=24 (+S2p offset layout)

static __device__ float g_p0[NCTA];
static __device__ float g_p1[NCTA];

// ---------------------------------------------------------------------------
// scalar helpers
// ---------------------------------------------------------------------------
__device__ __forceinline__ float tanh_hw(float x) {
    float r; asm("tanh.approx.f32 %0, %1;" : "=f"(r) : "f"(x)); return r;
}

// pack (lo,hi) floats -> bf16x2 (element 0 in low 16 bits)
__device__ __forceinline__ u32 cvt2(float lo, float hi) {
    u32 r; asm("cvt.rn.bf16x2.f32 %0, %1, %2;" : "=r"(r) : "f"(hi), "f"(lo)); return r;
}
// split (v0,v1) into hi/lo bf16x2 pair
__device__ __forceinline__ void hilo(float v0, float v1, u32& h, u32& l) {
    h = cvt2(v0, v1);
    float h0 = __uint_as_float(h << 16);
    float h1 = __uint_as_float(h & 0xFFFF0000u);
    l = cvt2(v0 - h0, v1 - h1);
}

// m16n8k16 bf16 MMA, fp32 accum in place
__device__ __forceinline__ void mma16816(float* c, u32 a0, u32 a1, u32 a2, u32 a3,
                                         u32 b0, u32 b1) {
    asm volatile(
        "mma.sync.aligned.m16n8k16.row.col.f32.bf16.bf16.f32 "
        "{%0,%1,%2,%3}, {%4,%5,%6,%7}, {%8,%9}, {%0,%1,%2,%3};"
        : "+f"(c[0]), "+f"(c[1]), "+f"(c[2]), "+f"(c[3])
        : "r"(a0), "r"(a1), "r"(a2), "r"(a3), "r"(b0), "r"(b1));
}

// ---------------------------------------------------------------------------
// warp-level batched GEMV stage:
//   out[32, NT*8] (+oofs cols) = act[32, KC*16] (@ jofs) @ W  (+ bias)
// act: hi/lo bf16x2, row stride AST. wf: fragment table [kc][nt][lane] uint4
// = {whi0, whi1, wlo0, wlo1}. 3 passes: ah*wh + al*wh + ah*wl.
// ---------------------------------------------------------------------------
template <int KC, int NT>
__device__ __forceinline__ void wstage(const u32* aH, const u32* aL, int jofs,
                                       const uint4* wf, const float* bias,
                                       float* ob, int oofs, int lane)
{
    const int grp = lane >> 2, qid = lane & 3;
#pragma unroll
    for (int mt = 0; mt < 2; mt++) {
        const int r0 = mt * 16 + grp;
        float c[NT][4];
#pragma unroll
        for (int nt = 0; nt < NT; nt++) {
            int col = nt * 8 + 2 * qid;
            float b0 = bias ? bias[col] : 0.0f;
            float b1 = bias ? bias[col + 1] : 0.0f;
            c[nt][0] = b0; c[nt][1] = b1; c[nt][2] = b0; c[nt][3] = b1;
        }
#pragma unroll
        for (int kc = 0; kc < KC; kc++) {
            int jb = kc * 8 + qid + jofs;
            u32 ah0 = aH[r0 * AST + jb];
            u32 ah1 = aH[(r0 + 8) * AST + jb];
            u32 ah2 = aH[r0 * AST + jb + 4];
            u32 ah3 = aH[(r0 + 8) * AST + jb + 4];
            u32 al0 = aL[r0 * AST + jb];
            u32 al1 = aL[(r0 + 8) * AST + jb];
            u32 al2 = aL[r0 * AST + jb + 4];
            u32 al3 = aL[(r0 + 8) * AST + jb + 4];
#pragma unroll
            for (int nt = 0; nt < NT; nt++) {
                uint4 w = wf[(kc * NT + nt) * 32 + lane];
                mma16816(c[nt], ah0, ah1, ah2, ah3, w.x, w.y);
                mma16816(c[nt], al0, al1, al2, al3, w.x, w.y);
                mma16816(c[nt], ah0, ah1, ah2, ah3, w.z, w.w);
            }
        }
#pragma unroll
        for (int nt = 0; nt < NT; nt++) {
            int col = oofs + nt * 8 + 2 * qid;
            *reinterpret_cast<float2*>(ob + r0 * OST + col) =
                make_float2(c[nt][0], c[nt][1]);
            *reinterpret_cast<float2*>(ob + (r0 + 8) * OST + col) =
                make_float2(c[nt][2], c[nt][3]);
        }
    }
}

// write this thread's activation row: PAIRS value-pairs, zero pad to PADTO
template <int PAIRS, int PADTO>
__device__ __forceinline__ void wact(u32* aH, u32* aL, int lane, const float* v) {
    u32* ph = aH + lane * AST;
    u32* pl = aL + lane * AST;
#pragma unroll
    for (int j = 0; j < PAIRS; j++) {
        u32 h, l; hilo(v[2 * j], v[2 * j + 1], h, l);
        ph[j] = h; pl[j] = l;
    }
#pragma unroll
    for (int j = PAIRS; j < PADTO; j++) { ph[j] = 0u; pl[j] = 0u; }
}

// split write for the z/phi 10+10 hidden vectors: z at pairs 0..4 (pad to 8),
// phi at pairs 8..12 (pad to 16)
__device__ __forceinline__ void wact_split20(u32* aH, u32* aL, int lane, const float* v) {
    u32* ph = aH + lane * AST;
    u32* pl = aL + lane * AST;
#pragma unroll
    for (int j = 0; j < 5; j++) {
        u32 h, l; hilo(v[2 * j], v[2 * j + 1], h, l);
        ph[j] = h; pl[j] = l;
    }
#pragma unroll
    for (int j = 5; j < 8; j++) { ph[j] = 0u; pl[j] = 0u; }
#pragma unroll
    for (int j = 0; j < 5; j++) {
        u32 h, l; hilo(v[10 + 2 * j], v[11 + 2 * j], h, l);
        ph[8 + j] = h; pl[8 + j] = l;
    }
#pragma unroll
    for (int j = 13; j < 16; j++) { ph[j] = 0u; pl[j] = 0u; }
}

template <int NV>
__device__ __forceinline__ void rdout(const float* ob, int lane, float* o) {
#pragma unroll
    for (int i = 0; i < NV / 2; i++) {
        float2 t = *reinterpret_cast<const float2*>(ob + lane * OST + 2 * i);
        o[2 * i] = t.x; o[2 * i + 1] = t.y;
    }
}

// ---------------------------------------------------------------------------
// main kernel: 128 threads = 128 trajectories; warp = autonomous 32-row tile
// ---------------------------------------------------------------------------
__global__ void __launch_bounds__(CTA_THREADS, 2) sim_kernel(
    const float* __restrict__ dw, const float* __restrict__ X0,
    const float* __restrict__ A,  const float* __restrict__ Bm,
    const float* __restrict__ Cm, const float* __restrict__ Dm,
    const float* __restrict__ pW1, const float* __restrict__ pb1,
    const float* __restrict__ pW2, const float* __restrict__ pb2,
    const float* __restrict__ pW3, const float* __restrict__ pb3,
    const float* __restrict__ zW1, const float* __restrict__ zb1,
    const float* __restrict__ zW2, const float* __restrict__ zb2,
    const float* __restrict__ zW3, const float* __restrict__ zb3,
    const float* __restrict__ yW1, const float* __restrict__ yb1,
    const float* __restrict__ yW2, const float* __restrict__ yb2,
    const float* __restrict__ yW3, const float* __restrict__ yb3)
{
    // tiles: 0-1 P1 | 2-3 P2 | 4-5 P3 | 6-8 S1 | 9-10 S2z | 11-12 S2p
    //        13-14 S3z | 15 S3p | 16-21 S4 | 22-25 S5a | 26-29 S5b
    __shared__ uint4 wfrag[30 * 32];          // 15.4 KB
    __shared__ float sbias[144];
    __shared__ float sb1[24], sw1[24];
    __shared__ float biasS1[4][24];
    __shared__ u32 sActH[4][32 * AST];        // 8.7 KB
    __shared__ u32 sActL[4][32 * AST];        // 8.7 KB
    __shared__ float sOut[4][32 * OST];       // 13.3 KB
    __shared__ float r0s[4], r1s[4];

    const int tid = threadIdx.x;
    const int wid = tid >> 5;
    const int lane = tid & 31;

    // ---- bias tables ----
    for (int i = tid; i < 144; i += CTA_THREADS) {
        float b = 0.0f;
        if (i < 16)        { if (i < 10) b = yb1[i]; }
        else if (i < 32)   { if (i - 16 < 10) b = yb2[i - 16]; }
        else if (i < 48)   { b = yb3[i - 32]; }
        else if (i < 64)   { if (i - 48 < 10) b = zb2[i - 48]; }
        else if (i < 80)   { if (i - 64 < 10) b = pb2[i - 64]; }
        else if (i < 96)   { b = zb3[i - 80]; }
        else if (i < 112)  { if (i - 96 < 8) b = pb3[i - 96]; }
        else if (i < 128)  { b = GAMMA_F; }
        else               { b = SIGMA_F; }
        sbias[i] = b;
    }
    if (tid < 24) {
        int n = tid;
        sb1[n] = (n < 10) ? zb1[n] : ((n < 20) ? pb1[n - 10] : 0.0f);
        sw1[n] = (n < 10) ? zW1[n] : ((n < 20) ? pW1[n - 10] : 0.0f);
    }

    // ---- weight fragment tables ----
    for (int idx = tid; idx < 30 * 32; idx += CTA_THREADS) {
        int tile = idx >> 5, ln = idx & 31;
        int stage, kc, nt;
        if      (tile < 2)  { stage = 0;  kc = 0; nt = tile; }
        else if (tile < 4)  { stage = 1;  kc = 0; nt = tile - 2; }
        else if (tile < 6)  { stage = 2;  kc = 0; nt = tile - 4; }
        else if (tile < 9)  { stage = 3;  kc = 0; nt = tile - 6; }
        else if (tile < 11) { stage = 4;  kc = 0; nt = tile - 9; }
        else if (tile < 13) { stage = 5;  kc = 0; nt = tile - 11; }
        else if (tile < 15) { stage = 6;  kc = 0; nt = tile - 13; }
        else if (tile < 16) { stage = 7;  kc = 0; nt = 0; }
        else if (tile < 22) { int r = tile - 16; stage = 8;  kc = r / 3; nt = r % 3; }
        else if (tile < 26) { int r = tile - 22; stage = 9;  kc = r / 2; nt = r % 2; }
        else                { int r = tile - 26; stage = 10; kc = r / 2; nt = r % 2; }
        int n = nt * 8 + (ln >> 2);
        int k0 = kc * 16 + (ln & 3) * 2;
        float w[4];
#pragma unroll
        for (int q = 0; q < 4; q++) {
            int k = k0 + (q & 1) + (q >> 1) * 8;
            float val = 0.0f;
            switch (stage) {
                case 0: if (k < 16 && n < 10) val = yW1[k * 10 + n]; break;
                case 1: if (k < 10 && n < 10) val = yW2[k * 10 + n]; break;
                case 2: if (k < 10 && n < 16) val = yW3[k * 16 + n]; break;
                case 3:
                    if (k < 16) {
                        if (n < 10)      val = zW1[(k + 1) * 10 + n];
                        else if (n < 20) val = pW1[(k + 1) * 10 + (n - 10)];
                    }
                    break;
                case 4: if (k < 10 && n < 10) val = zW2[k * 10 + n]; break;
                case 5: if (k < 10 && n < 10) val = pW2[k * 10 + n]; break;
                case 6: if (k < 10 && n < 16) val = zW3[k * 16 + n]; break;
                case 7: if (k < 10 && n < 8)  val = pW3[k * 8 + n]; break;
                case 8:
                    if (n < 16)      val = (k < 16) ? A[k * 16 + n]  : Cm[(k - 16) * 16 + n];
                    else if (n < 24) val = (k < 16) ? Bm[k * 8 + (n - 16)] : Dm[(k - 16) * 8 + (n - 16)];
                    break;
                case 9:   // S5a: drift = X@A^T + u@B^T
                    if (n < 16) {
                        if (k < 16)      val = A[n * 16 + k];
                        else if (k < 24) val = Bm[n * 8 + (k - 16)];
                    }
                    break;
                default:  // S5b: diff = X@C^T + u@D^T
                    if (n < 16) {
                        if (k < 16)      val = Cm[n * 16 + k];
                        else if (k < 24) val = Dm[n * 8 + (k - 16)];
                    }
                    break;
            }
            w[q] = val;
        }
        u32 h0, l0, h1, l1;
        hilo(w[0], w[1], h0, l0);
        hilo(w[2], w[3], h1, l1);
        wfrag[idx] = make_uint4(h0, h1, l0, l1);
    }
    __syncthreads();

    const int traj = blockIdx.x * CTA_THREADS + tid;
    u32* aH = sActH[wid];
    u32* aL = sActL[wid];
    float* ob = sOut[wid];

    float X[16], Y[16];
#pragma unroll
    for (int j = 0; j < 4; j++) {
        float4 v = reinterpret_cast<const float4*>(X0 + (size_t)traj * 16)[j];
        X[4 * j + 0] = v.x; X[4 * j + 1] = v.y;
        X[4 * j + 2] = v.z; X[4 * j + 3] = v.w;
    }

    // ---- prologue: Y = MLP_Y0(X0) ----
    {
        float o[16], hv[10];
        wact<8, 8>(aH, aL, lane, X);
        __syncwarp();
        wstage<1, 2>(aH, aL, 0, &wfrag[0], &sbias[0], ob, 0, lane);
        __syncwarp();
        rdout<10>(ob, lane, o);
#pragma unroll
        for (int j = 0; j < 10; j++) hv[j] = tanh_hw(o[j]);
        __syncwarp();
        wact<5, 8>(aH, aL, lane, hv);
        __syncwarp();
        wstage<1, 2>(aH, aL, 0, &wfrag[2 * 32], &sbias[16], ob, 0, lane);
        __syncwarp();
        rdout<10>(ob, lane, o);
#pragma unroll
        for (int j = 0; j < 10; j++) hv[j] = tanh_hw(o[j]);
        __syncwarp();
        wact<5, 8>(aH, aL, lane, hv);
        __syncwarp();
        wstage<1, 2>(aH, aL, 0, &wfrag[4 * 32], &sbias[32], ob, 0, lane);
        __syncwarp();
        rdout<16>(ob, lane, Y);
        __syncwarp();
    }

    float lc = 0.0f;

    for (int t = 0; t < T_STEPS; t++) {
        float tt = (float)t * DT_F;
        float dwi = __ldg(dw + (size_t)t * BATCH + traj);

        // per-warp S1 bias: b + t * W_row_t
        if (lane < 24) biasS1[wid][lane] = fmaf(tt, sw1[lane], sb1[lane]);
        __syncwarp();

        float o[24], hv[20];

        // ---- S1: X -> (hz | hp) ----
        wact<8, 8>(aH, aL, lane, X);
        __syncwarp();
        wstage<1, 3>(aH, aL, 0, &wfrag[6 * 32], biasS1[wid], ob, 0, lane);
        __syncwarp();
        rdout<20>(ob, lane, o);
#pragma unroll
        for (int j = 0; j < 20; j++) hv[j] = tanh_hw(o[j]);
        __syncwarp();

        // ---- S2: block-diagonal z / phi ----
        wact_split20(aH, aL, lane, hv);
        __syncwarp();
        wstage<1, 2>(aH, aL, 0, &wfrag[9 * 32],  &sbias[48], ob, 0,  lane);
        wstage<1, 2>(aH, aL, 8, &wfrag[11 * 32], &sbias[64], ob, 10, lane);
        __syncwarp();
        rdout<20>(ob, lane, o);
#pragma unroll
        for (int j = 0; j < 20; j++) hv[j] = tanh_hw(o[j]);
        __syncwarp();

        // ---- S3: z -> Zv (cols 0..15), phi -> u (cols 16..23) ----
        wact_split20(aH, aL, lane, hv);
        __syncwarp();
        wstage<1, 2>(aH, aL, 0, &wfrag[13 * 32], &sbias[80], ob, 0,  lane);
        wstage<1, 1>(aH, aL, 8, &wfrag[15 * 32], &sbias[96], ob, 16, lane);
        __syncwarp();
        float Zu[24];
        rdout<24>(ob, lane, Zu);   // Zv = Zu[0..15], u = Zu[16..23]
        __syncwarp();

        // ---- S4: [Y | Zv] -> [Y@A+Zv@C | Y@B+Zv@D] ----
        {
            float yz[32];
#pragma unroll
            for (int i = 0; i < 16; i++) { yz[i] = Y[i]; yz[16 + i] = Zu[i]; }
            wact<16, 16>(aH, aL, lane, yz);
        }
        __syncwarp();
        wstage<2, 3>(aH, aL, 0, &wfrag[16 * 32], nullptr, ob, 0, lane);
        __syncwarp();
        float oy[24];
        rdout<24>(ob, lane, oy);
        __syncwarp();

        // ---- S5: [X | u] -> drift then diff ----
        {
            float xu[24];
#pragma unroll
            for (int i = 0; i < 16; i++) xu[i] = X[i];
#pragma unroll
            for (int m = 0; m < 8; m++) xu[16 + m] = Zu[16 + m];
            wact<12, 16>(aH, aL, lane, xu);
        }
        __syncwarp();
        wstage<2, 2>(aH, aL, 0, &wfrag[22 * 32], &sbias[112], ob, 0, lane);
        __syncwarp();
        float drift[16];
        rdout<16>(ob, lane, drift);
        __syncwarp();
        wstage<2, 2>(aH, aL, 0, &wfrag[26 * 32], &sbias[128], ob, 0, lane);
        __syncwarp();
        float diff[16];
        rdout<16>(ob, lane, diff);
        __syncwarp();

        // ---- lc: dH = u + Y@B + Zv@D ----
        {
            float ss = 0.0f;
#pragma unroll
            for (int m = 0; m < 8; m++) {
                float dh = oy[16 + m] + Zu[16 + m];
                ss = fmaf(dh, dh, ss);
            }
            float w = (t == 0 || t == T_STEPS - 1) ? LC_SCALE : 2.0f * LC_SCALE;
            lc = fmaf(w, ss, lc);
        }

        // ---- state updates (Y uses old X) ----
#pragma unroll
        for (int i = 0; i < 16; i++)
            Y[i] = fmaf(dwi, Zu[i], fmaf(-(oy[i] + X[i]), DT_F, Y[i]));
#pragma unroll
        for (int i = 0; i < 16; i++)
            X[i] = fmaf(dwi, diff[i], fmaf(drift[i], DT_F, X[i]));
    }

    float lb = 0.0f;
#pragma unroll
    for (int i = 0; i < 16; i++) {
        float d = Y[i] - X[i];
        lb = fmaf(d, d, lb);
    }

    // ---- block reduction (4 warps) ----
#pragma unroll
    for (int off = 16; off; off >>= 1) {
        lb += __shfl_down_sync(0xffffffffu, lb, off);
        lc += __shfl_down_sync(0xffffffffu, lc, off);
    }
    if (lane == 0) { r0s[wid] = lb; r1s[wid] = lc; }
    __syncthreads();
    if (tid == 0) {
        g_p0[blockIdx.x] = (r0s[0] + r0s[1]) + (r0s[2] + r0s[3]);
        g_p1[blockIdx.x] = (r1s[0] + r1s[1]) + (r1s[2] + r1s[3]);
    }
}

// ---------------------------------------------------------------------------
// final reduction: NCTA (=256) partials -> 2 means
// ---------------------------------------------------------------------------
__global__ void __launch_bounds__(NCTA) finalize_kernel(float* __restrict__ out) {
    int tid = threadIdx.x;
    float a = g_p0[tid];
    float c = g_p1[tid];
#pragma unroll
    for (int o = 16; o; o >>= 1) {
        a += __shfl_down_sync(0xffffffffu, a, o);
        c += __shfl_down_sync(0xffffffffu, c, o);
    }
    __shared__ float sa[NCTA / 32], sc[NCTA / 32];
    int warp = tid >> 5, lane = tid & 31;
    if (lane == 0) { sa[warp] = a; sc[warp] = c; }
    __syncthreads();
    if (warp == 0) {
        a = (lane < NCTA / 32) ? sa[lane] : 0.0f;
        c = (lane < NCTA / 32) ? sc[lane] : 0.0f;
#pragma unroll
        for (int o = 4; o; o >>= 1) {
            a += __shfl_down_sync(0xffffffffu, a, o);
            c += __shfl_down_sync(0xffffffffu, c, o);
        }
        if (lane == 0) {
            out[0] = a * (1.0f / (float)BATCH);
            out[1] = c * (1.0f / (float)BATCH);
        }
    }
}

extern "C" void kernel_launch(void* const* d_in, const int* in_sizes, int n_in,
                              void* d_out, int out_size) {
    const float* dw  = (const float*)d_in[0];
    const float* X0  = (const float*)d_in[1];
    const float* A   = (const float*)d_in[2];
    const float* Bm  = (const float*)d_in[3];
    const float* Cm  = (const float*)d_in[4];
    const float* Dm  = (const float*)d_in[5];
    const float* pW1 = (const float*)d_in[6];
    const float* pb1 = (const float*)d_in[7];
    const float* pW2 = (const float*)d_in[8];
    const float* pb2 = (const float*)d_in[9];
    const float* pW3 = (const float*)d_in[10];
    const float* pb3 = (const float*)d_in[11];
    const float* zW1 = (const float*)d_in[12];
    const float* zb1 = (const float*)d_in[13];
    const float* zW2 = (const float*)d_in[14];
    const float* zb2 = (const float*)d_in[15];
    const float* zW3 = (const float*)d_in[16];
    const float* zb3 = (const float*)d_in[17];
    const float* yW1 = (const float*)d_in[18];
    const float* yb1 = (const float*)d_in[19];
    const float* yW2 = (const float*)d_in[20];
    const float* yb2 = (const float*)d_in[21];
    const float* yW3 = (const float*)d_in[22];
    const float* yb3 = (const float*)d_in[23];

    sim_kernel<<<NCTA, CTA_THREADS>>>(dw, X0, A, Bm, Cm, Dm,
                                      pW1, pb1, pW2, pb2, pW3, pb3,
                                      zW1, zb1, zW2, zb2, zW3, zb3,
                                      yW1, yb1, yW2, yb2, yW3, yb3);
    finalize_kernel<<<1, NCTA>>>((float*)d_out);
}

// round 13
// speedup vs baseline: 1.4776x; 1.0495x over previous
#include <cuda_runtime.h>
#include <cuda_bf16.h>
#include <cstdint>

using u32 = unsigned int;

#define T_STEPS 50
#define BATCH 32768
#define CTA_THREADS 128
#define NCTA (BATCH / CTA_THREADS)   // 256

#define DT_F 0.01f
#define GAMMA_F 0.1f
#define SIGMA_F 0.2f
#define LC_SCALE (0.5f * 0.01f * 0.25f)   // 0.5*DT*TAU^2

#define AST 17   // act row stride (u32 pairs), odd -> conflict-free writes
#define OST 36   // out row stride (floats), fits 32-col fused S5 output

static __device__ float g_p0[NCTA];
static __device__ float g_p1[NCTA];

// dynamic shared memory layout (~51.2 KB)
struct SmemLayout {
    uint4 wfrag[30 * 32];        // 15360 B
    float sbias[144];
    float sb1[24], sw1[24];
    float biasS1[4][24];
    u32   aH[4][32 * AST];       // 8704 B
    u32   aL[4][32 * AST];       // 8704 B
    float sout[4][32 * OST];     // 18432 B
    float r0s[4], r1s[4];
};

// ---------------------------------------------------------------------------
// scalar helpers
// ---------------------------------------------------------------------------
__device__ __forceinline__ float tanh_hw(float x) {
    float r; asm("tanh.approx.f32 %0, %1;" : "=f"(r) : "f"(x)); return r;
}

__device__ __forceinline__ u32 cvt2(float lo, float hi) {
    u32 r; asm("cvt.rn.bf16x2.f32 %0, %1, %2;" : "=r"(r) : "f"(hi), "f"(lo)); return r;
}
__device__ __forceinline__ void hilo(float v0, float v1, u32& h, u32& l) {
    h = cvt2(v0, v1);
    float h0 = __uint_as_float(h << 16);
    float h1 = __uint_as_float(h & 0xFFFF0000u);
    l = cvt2(v0 - h0, v1 - h1);
}

__device__ __forceinline__ void mma16816(float* c, u32 a0, u32 a1, u32 a2, u32 a3,
                                         u32 b0, u32 b1) {
    asm volatile(
        "mma.sync.aligned.m16n8k16.row.col.f32.bf16.bf16.f32 "
        "{%0,%1,%2,%3}, {%4,%5,%6,%7}, {%8,%9}, {%0,%1,%2,%3};"
        : "+f"(c[0]), "+f"(c[1]), "+f"(c[2]), "+f"(c[3])
        : "r"(a0), "r"(a1), "r"(a2), "r"(a3), "r"(b0), "r"(b1));
}

// ---------------------------------------------------------------------------
// warp-level batched GEMV stage, split accumulators:
//   cH accumulates ah*wh (init bias); cL accumulates al*wh and ah*wl (init 0)
//   out = cH + cL
// ---------------------------------------------------------------------------
template <int KC, int NT>
__device__ __forceinline__ void wstage(const u32* aH, const u32* aL, int jofs,
                                       const uint4* wf, const float* bias,
                                       float* ob, int oofs, int lane)
{
    const int grp = lane >> 2, qid = lane & 3;
#pragma unroll
    for (int mt = 0; mt < 2; mt++) {
        const int r0 = mt * 16 + grp;
        float cH[NT][4], cL[NT][4];
#pragma unroll
        for (int nt = 0; nt < NT; nt++) {
            int col = nt * 8 + 2 * qid;
            float b0 = bias ? bias[col] : 0.0f;
            float b1 = bias ? bias[col + 1] : 0.0f;
            cH[nt][0] = b0; cH[nt][1] = b1; cH[nt][2] = b0; cH[nt][3] = b1;
            cL[nt][0] = 0.0f; cL[nt][1] = 0.0f; cL[nt][2] = 0.0f; cL[nt][3] = 0.0f;
        }
#pragma unroll
        for (int kc = 0; kc < KC; kc++) {
            int jb = kc * 8 + qid + jofs;
            u32 ah0 = aH[r0 * AST + jb];
            u32 ah1 = aH[(r0 + 8) * AST + jb];
            u32 ah2 = aH[r0 * AST + jb + 4];
            u32 ah3 = aH[(r0 + 8) * AST + jb + 4];
            u32 al0 = aL[r0 * AST + jb];
            u32 al1 = aL[(r0 + 8) * AST + jb];
            u32 al2 = aL[r0 * AST + jb + 4];
            u32 al3 = aL[(r0 + 8) * AST + jb + 4];
#pragma unroll
            for (int nt = 0; nt < NT; nt++) {
                uint4 w = wf[(kc * NT + nt) * 32 + lane];
                mma16816(cH[nt], ah0, ah1, ah2, ah3, w.x, w.y);
                mma16816(cL[nt], al0, al1, al2, al3, w.x, w.y);
                mma16816(cL[nt], ah0, ah1, ah2, ah3, w.z, w.w);
            }
        }
#pragma unroll
        for (int nt = 0; nt < NT; nt++) {
            int col = oofs + nt * 8 + 2 * qid;
            *reinterpret_cast<float2*>(ob + r0 * OST + col) =
                make_float2(cH[nt][0] + cL[nt][0], cH[nt][1] + cL[nt][1]);
            *reinterpret_cast<float2*>(ob + (r0 + 8) * OST + col) =
                make_float2(cH[nt][2] + cL[nt][2], cH[nt][3] + cL[nt][3]);
        }
    }
}

template <int PAIRS, int PADTO>
__device__ __forceinline__ void wact(u32* aH, u32* aL, int lane, const float* v) {
    u32* ph = aH + lane * AST;
    u32* pl = aL + lane * AST;
#pragma unroll
    for (int j = 0; j < PAIRS; j++) {
        u32 h, l; hilo(v[2 * j], v[2 * j + 1], h, l);
        ph[j] = h; pl[j] = l;
    }
#pragma unroll
    for (int j = PAIRS; j < PADTO; j++) { ph[j] = 0u; pl[j] = 0u; }
}

// split write for z/phi 10+10 hidden: z pairs 0..4 (pad 8), phi pairs 8..12 (pad 16)
__device__ __forceinline__ void wact_split20(u32* aH, u32* aL, int lane, const float* v) {
    u32* ph = aH + lane * AST;
    u32* pl = aL + lane * AST;
#pragma unroll
    for (int j = 0; j < 5; j++) {
        u32 h, l; hilo(v[2 * j], v[2 * j + 1], h, l);
        ph[j] = h; pl[j] = l;
    }
#pragma unroll
    for (int j = 5; j < 8; j++) { ph[j] = 0u; pl[j] = 0u; }
#pragma unroll
    for (int j = 0; j < 5; j++) {
        u32 h, l; hilo(v[10 + 2 * j], v[11 + 2 * j], h, l);
        ph[8 + j] = h; pl[8 + j] = l;
    }
#pragma unroll
    for (int j = 13; j < 16; j++) { ph[j] = 0u; pl[j] = 0u; }
}

template <int NV>
__device__ __forceinline__ void rdout(const float* ob, int lane, float* o, int ofs) {
#pragma unroll
    for (int i = 0; i < NV / 2; i++) {
        float2 t = *reinterpret_cast<const float2*>(ob + lane * OST + ofs + 2 * i);
        o[2 * i] = t.x; o[2 * i + 1] = t.y;
    }
}

// ---------------------------------------------------------------------------
// main kernel: 128 threads = 128 trajectories; warp = autonomous 32-row tile
// ---------------------------------------------------------------------------
__global__ void __launch_bounds__(CTA_THREADS, 2) sim_kernel(
    const float* __restrict__ dw, const float* __restrict__ X0,
    const float* __restrict__ A,  const float* __restrict__ Bm,
    const float* __restrict__ Cm, const float* __restrict__ Dm,
    const float* __restrict__ pW1, const float* __restrict__ pb1,
    const float* __restrict__ pW2, const float* __restrict__ pb2,
    const float* __restrict__ pW3, const float* __restrict__ pb3,
    const float* __restrict__ zW1, const float* __restrict__ zb1,
    const float* __restrict__ zW2, const float* __restrict__ zb2,
    const float* __restrict__ zW3, const float* __restrict__ zb3,
    const float* __restrict__ yW1, const float* __restrict__ yb1,
    const float* __restrict__ yW2, const float* __restrict__ yb2,
    const float* __restrict__ yW3, const float* __restrict__ yb3)
{
    extern __shared__ char smem_raw[];
    SmemLayout* S = reinterpret_cast<SmemLayout*>(smem_raw);

    const int tid = threadIdx.x;
    const int wid = tid >> 5;
    const int lane = tid & 31;

    // ---- bias tables ----
    for (int i = tid; i < 144; i += CTA_THREADS) {
        float b = 0.0f;
        if (i < 16)        { if (i < 10) b = yb1[i]; }
        else if (i < 32)   { if (i - 16 < 10) b = yb2[i - 16]; }
        else if (i < 48)   { b = yb3[i - 32]; }
        else if (i < 64)   { if (i - 48 < 10) b = zb2[i - 48]; }
        else if (i < 80)   { if (i - 64 < 10) b = pb2[i - 64]; }
        else if (i < 96)   { b = zb3[i - 80]; }
        else if (i < 112)  { if (i - 96 < 8) b = pb3[i - 96]; }
        else if (i < 128)  { b = GAMMA_F; }
        else               { b = SIGMA_F; }
        S->sbias[i] = b;
    }
    if (tid < 24) {
        int n = tid;
        S->sb1[n] = (n < 10) ? zb1[n] : ((n < 20) ? pb1[n - 10] : 0.0f);
        S->sw1[n] = (n < 10) ? zW1[n] : ((n < 20) ? pW1[n - 10] : 0.0f);
    }

    // ---- weight fragment tables ----
    // tiles: 0-1 P1 | 2-3 P2 | 4-5 P3 | 6-8 S1 | 9-10 S2z | 11-12 S2p
    //        13-14 S3z | 15 S3p | 16-21 S4 (KC2,NT3) | 22-29 S5 fused (KC2,NT4)
    for (int idx = tid; idx < 30 * 32; idx += CTA_THREADS) {
        int tile = idx >> 5, ln = idx & 31;
        int stage, kc, nt;
        if      (tile < 2)  { stage = 0;  kc = 0; nt = tile; }
        else if (tile < 4)  { stage = 1;  kc = 0; nt = tile - 2; }
        else if (tile < 6)  { stage = 2;  kc = 0; nt = tile - 4; }
        else if (tile < 9)  { stage = 3;  kc = 0; nt = tile - 6; }
        else if (tile < 11) { stage = 4;  kc = 0; nt = tile - 9; }
        else if (tile < 13) { stage = 5;  kc = 0; nt = tile - 11; }
        else if (tile < 15) { stage = 6;  kc = 0; nt = tile - 13; }
        else if (tile < 16) { stage = 7;  kc = 0; nt = 0; }
        else if (tile < 22) { int r = tile - 16; stage = 8;  kc = r / 3; nt = r % 3; }
        else                { int r = tile - 22; stage = 9;  kc = r / 4; nt = r % 4; }
        int n = nt * 8 + (ln >> 2);
        int k0 = kc * 16 + (ln & 3) * 2;
        float w[4];
#pragma unroll
        for (int q = 0; q < 4; q++) {
            int k = k0 + (q & 1) + (q >> 1) * 8;
            float val = 0.0f;
            switch (stage) {
                case 0: if (k < 16 && n < 10) val = yW1[k * 10 + n]; break;
                case 1: if (k < 10 && n < 10) val = yW2[k * 10 + n]; break;
                case 2: if (k < 10 && n < 16) val = yW3[k * 16 + n]; break;
                case 3:
                    if (k < 16) {
                        if (n < 10)      val = zW1[(k + 1) * 10 + n];
                        else if (n < 20) val = pW1[(k + 1) * 10 + (n - 10)];
                    }
                    break;
                case 4: if (k < 10 && n < 10) val = zW2[k * 10 + n]; break;
                case 5: if (k < 10 && n < 10) val = pW2[k * 10 + n]; break;
                case 6: if (k < 10 && n < 16) val = zW3[k * 16 + n]; break;
                case 7: if (k < 10 && n < 8)  val = pW3[k * 8 + n]; break;
                case 8:
                    if (n < 16)      val = (k < 16) ? A[k * 16 + n]  : Cm[(k - 16) * 16 + n];
                    else if (n < 24) val = (k < 16) ? Bm[k * 8 + (n - 16)] : Dm[(k - 16) * 8 + (n - 16)];
                    break;
                default: {   // S5 fused: n<16 drift (A^T,B^T), n>=16 diff (C^T,D^T)
                    int nn = n & 15;
                    if (n < 16) {
                        if (k < 16)      val = A[nn * 16 + k];
                        else if (k < 24) val = Bm[nn * 8 + (k - 16)];
                    } else {
                        if (k < 16)      val = Cm[nn * 16 + k];
                        else if (k < 24) val = Dm[nn * 8 + (k - 16)];
                    }
                    break;
                }
            }
            w[q] = val;
        }
        u32 h0, l0, h1, l1;
        hilo(w[0], w[1], h0, l0);
        hilo(w[2], w[3], h1, l1);
        S->wfrag[idx] = make_uint4(h0, h1, l0, l1);
    }
    __syncthreads();

    const int traj = blockIdx.x * CTA_THREADS + tid;
    u32* aH = S->aH[wid];
    u32* aL = S->aL[wid];
    float* ob = S->sout[wid];
    const uint4* WF = S->wfrag;

    float X[16], Y[16];
#pragma unroll
    for (int j = 0; j < 4; j++) {
        float4 v = reinterpret_cast<const float4*>(X0 + (size_t)traj * 16)[j];
        X[4 * j + 0] = v.x; X[4 * j + 1] = v.y;
        X[4 * j + 2] = v.z; X[4 * j + 3] = v.w;
    }

    // ---- prologue: Y = MLP_Y0(X0) ----
    {
        float o[16], hv[10];
        wact<8, 8>(aH, aL, lane, X);
        __syncwarp();
        wstage<1, 2>(aH, aL, 0, &WF[0], &S->sbias[0], ob, 0, lane);
        __syncwarp();
        rdout<10>(ob, lane, o, 0);
#pragma unroll
        for (int j = 0; j < 10; j++) hv[j] = tanh_hw(o[j]);
        __syncwarp();
        wact<5, 8>(aH, aL, lane, hv);
        __syncwarp();
        wstage<1, 2>(aH, aL, 0, &WF[2 * 32], &S->sbias[16], ob, 0, lane);
        __syncwarp();
        rdout<10>(ob, lane, o, 0);
#pragma unroll
        for (int j = 0; j < 10; j++) hv[j] = tanh_hw(o[j]);
        __syncwarp();
        wact<5, 8>(aH, aL, lane, hv);
        __syncwarp();
        wstage<1, 2>(aH, aL, 0, &WF[4 * 32], &S->sbias[32], ob, 0, lane);
        __syncwarp();
        rdout<16>(ob, lane, Y, 0);
        __syncwarp();
    }

    float lc = 0.0f;

    for (int t = 0; t < T_STEPS; t++) {
        float tt = (float)t * DT_F;
        float dwi = __ldg(dw + (size_t)t * BATCH + traj);

        if (lane < 24) S->biasS1[wid][lane] = fmaf(tt, S->sw1[lane], S->sb1[lane]);
        __syncwarp();

        float o[24], hv[20];

        // ---- S1: X -> (hz | hp) ----
        wact<8, 8>(aH, aL, lane, X);
        __syncwarp();
        wstage<1, 3>(aH, aL, 0, &WF[6 * 32], S->biasS1[wid], ob, 0, lane);
        __syncwarp();
        rdout<20>(ob, lane, o, 0);
#pragma unroll
        for (int j = 0; j < 20; j++) hv[j] = tanh_hw(o[j]);
        __syncwarp();

        // ---- S2: z at out 0..9, phi at out 16..25 (one sync) ----
        wact_split20(aH, aL, lane, hv);
        __syncwarp();
        wstage<1, 2>(aH, aL, 0, &WF[9 * 32],  &S->sbias[48], ob, 0,  lane);
        wstage<1, 2>(aH, aL, 8, &WF[11 * 32], &S->sbias[64], ob, 16, lane);
        __syncwarp();
        rdout<10>(ob, lane, o, 0);
        rdout<10>(ob, lane, o + 10, 16);
#pragma unroll
        for (int j = 0; j < 20; j++) hv[j] = tanh_hw(o[j]);
        __syncwarp();

        // ---- S3: Zv at 0..15, u at 16..23 ----
        wact_split20(aH, aL, lane, hv);
        __syncwarp();
        wstage<1, 2>(aH, aL, 0, &WF[13 * 32], &S->sbias[80], ob, 0,  lane);
        wstage<1, 1>(aH, aL, 8, &WF[15 * 32], &S->sbias[96], ob, 16, lane);
        __syncwarp();
        float Zu[24];
        rdout<24>(ob, lane, Zu, 0);   // Zv = Zu[0..15], u = Zu[16..23]
        __syncwarp();

        // ---- S4: [Y | Zv] -> [Y@A+Zv@C | Y@B+Zv@D] ----
        {
            float yz[32];
#pragma unroll
            for (int i = 0; i < 16; i++) { yz[i] = Y[i]; yz[16 + i] = Zu[i]; }
            wact<16, 16>(aH, aL, lane, yz);
        }
        __syncwarp();
        wstage<2, 3>(aH, aL, 0, &WF[16 * 32], nullptr, ob, 0, lane);
        __syncwarp();
        float oy[24];
        rdout<24>(ob, lane, oy, 0);
        __syncwarp();

        // ---- S5 fused: [X | u] -> [drift | diff] in one stage ----
        {
            float xu[24];
#pragma unroll
            for (int i = 0; i < 16; i++) xu[i] = X[i];
#pragma unroll
            for (int m = 0; m < 8; m++) xu[16 + m] = Zu[16 + m];
            wact<12, 16>(aH, aL, lane, xu);
        }
        __syncwarp();
        wstage<2, 4>(aH, aL, 0, &WF[22 * 32], &S->sbias[112], ob, 0, lane);
        __syncwarp();
        float od[32];
        rdout<32>(ob, lane, od, 0);   // drift = od[0..15], diff = od[16..31]
        __syncwarp();

        // ---- lc: dH = u + Y@B + Zv@D ----
        {
            float ss = 0.0f;
#pragma unroll
            for (int m = 0; m < 8; m++) {
                float dh = oy[16 + m] + Zu[16 + m];
                ss = fmaf(dh, dh, ss);
            }
            float w = (t == 0 || t == T_STEPS - 1) ? LC_SCALE : 2.0f * LC_SCALE;
            lc = fmaf(w, ss, lc);
        }

        // ---- state updates (Y uses old X) ----
#pragma unroll
        for (int i = 0; i < 16; i++)
            Y[i] = fmaf(dwi, Zu[i], fmaf(-(oy[i] + X[i]), DT_F, Y[i]));
#pragma unroll
        for (int i = 0; i < 16; i++)
            X[i] = fmaf(dwi, od[16 + i], fmaf(od[i], DT_F, X[i]));
    }

    float lb = 0.0f;
#pragma unroll
    for (int i = 0; i < 16; i++) {
        float d = Y[i] - X[i];
        lb = fmaf(d, d, lb);
    }

    // ---- block reduction (4 warps) ----
#pragma unroll
    for (int off = 16; off; off >>= 1) {
        lb += __shfl_down_sync(0xffffffffu, lb, off);
        lc += __shfl_down_sync(0xffffffffu, lc, off);
    }
    if (lane == 0) { S->r0s[wid] = lb; S->r1s[wid] = lc; }
    __syncthreads();
    if (tid == 0) {
        g_p0[blockIdx.x] = (S->r0s[0] + S->r0s[1]) + (S->r0s[2] + S->r0s[3]);
        g_p1[blockIdx.x] = (S->r1s[0] + S->r1s[1]) + (S->r1s[2] + S->r1s[3]);
    }
}

// ---------------------------------------------------------------------------
// final reduction: NCTA (=256) partials -> 2 means
// ---------------------------------------------------------------------------
__global__ void __launch_bounds__(NCTA) finalize_kernel(float* __restrict__ out) {
    int tid = threadIdx.x;
    float a = g_p0[tid];
    float c = g_p1[tid];
#pragma unroll
    for (int o = 16; o; o >>= 1) {
        a += __shfl_down_sync(0xffffffffu, a, o);
        c += __shfl_down_sync(0xffffffffu, c, o);
    }
    __shared__ float sa[NCTA / 32], sc[NCTA / 32];
    int warp = tid >> 5, lane = tid & 31;
    if (lane == 0) { sa[warp] = a; sc[warp] = c; }
    __syncthreads();
    if (warp == 0) {
        a = (lane < NCTA / 32) ? sa[lane] : 0.0f;
        c = (lane < NCTA / 32) ? sc[lane] : 0.0f;
#pragma unroll
        for (int o = 4; o; o >>= 1) {
            a += __shfl_down_sync(0xffffffffu, a, o);
            c += __shfl_down_sync(0xffffffffu, c, o);
        }
        if (lane == 0) {
            out[0] = a * (1.0f / (float)BATCH);
            out[1] = c * (1.0f / (float)BATCH);
        }
    }
}

extern "C" void kernel_launch(void* const* d_in, const int* in_sizes, int n_in,
                              void* d_out, int out_size) {
    const float* dw  = (const float*)d_in[0];
    const float* X0  = (const float*)d_in[1];
    const float* A   = (const float*)d_in[2];
    const float* Bm  = (const float*)d_in[3];
    const float* Cm  = (const float*)d_in[4];
    const float* Dm  = (const float*)d_in[5];
    const float* pW1 = (const float*)d_in[6];
    const float* pb1 = (const float*)d_in[7];
    const float* pW2 = (const float*)d_in[8];
    const float* pb2 = (const float*)d_in[9];
    const float* pW3 = (const float*)d_in[10];
    const float* pb3 = (const float*)d_in[11];
    const float* zW1 = (const float*)d_in[12];
    const float* zb1 = (const float*)d_in[13];
    const float* zW2 = (const float*)d_in[14];
    const float* zb2 = (const float*)d_in[15];
    const float* zW3 = (const float*)d_in[16];
    const float* zb3 = (const float*)d_in[17];
    const float* yW1 = (const float*)d_in[18];
    const float* yb1 = (const float*)d_in[19];
    const float* yW2 = (const float*)d_in[20];
    const float* yb2 = (const float*)d_in[21];
    const float* yW3 = (const float*)d_in[22];
    const float* yb3 = (const float*)d_in[23];

    cudaFuncSetAttribute(sim_kernel, cudaFuncAttributeMaxDynamicSharedMemorySize,
                         (int)sizeof(SmemLayout));

    sim_kernel<<<NCTA, CTA_THREADS, sizeof(SmemLayout)>>>(
        dw, X0, A, Bm, Cm, Dm,
        pW1, pb1, pW2, pb2, pW3, pb3,
        zW1, zb1, zW2, zb2, zW3, zb3,
        yW1, yb1, yW2, yb2, yW3, yb3);
    finalize_kernel<<<1, NCTA>>>((float*)d_out);
}

// round 15
// speedup vs baseline: 2.1254x; 1.4384x over previous
#include <cuda_runtime.h>
#include <cuda_bf16.h>
#include <cstdint>

using u32 = unsigned int;

#define T_STEPS 50
#define BATCH 32768
#define CTA_THREADS 128
#define NCTA (BATCH / CTA_THREADS)   // 256

#define DT_F 0.01f
#define GAMMA_F 0.1f
#define SIGMA_F 0.2f
#define LC_SCALE (0.5f * 0.01f * 0.25f)   // 0.5*DT*TAU^2

static __device__ float g_p0[NCTA];
static __device__ float g_p1[NCTA];

// ---------------------------------------------------------------------------
// helpers
// ---------------------------------------------------------------------------
__device__ __forceinline__ float tanh_hw(float x) {
    float r; asm("tanh.approx.f32 %0, %1;" : "=f"(r) : "f"(x)); return r;
}
__device__ __forceinline__ u32 cvt2(float lo, float hi) {
    u32 r; asm("cvt.rn.bf16x2.f32 %0, %1, %2;" : "=r"(r) : "f"(hi), "f"(lo)); return r;
}
__device__ __forceinline__ void hilo(float v0, float v1, u32& h, u32& l) {
    h = cvt2(v0, v1);
    float h0 = __uint_as_float(h << 16);
    float h1 = __uint_as_float(h & 0xFFFF0000u);
    l = cvt2(v0 - h0, v1 - h1);
}
__device__ __forceinline__ void mma16816(float* c, u32 a0, u32 a1, u32 a2, u32 a3,
                                         u32 b0, u32 b1) {
    asm volatile(
        "mma.sync.aligned.m16n8k16.row.col.f32.bf16.bf16.f32 "
        "{%0,%1,%2,%3}, {%4,%5,%6,%7}, {%8,%9}, {%0,%1,%2,%3};"
        : "+f"(c[0]), "+f"(c[1]), "+f"(c[2]), "+f"(c[3])
        : "r"(a0), "r"(a1), "r"(a2), "r"(a3), "r"(b0), "r"(b1));
}

// pack an 8-float frag vector (tile0 c0..c3, tile1 c0..c3) into one A k-chunk
__device__ __forceinline__ void packA8(const float* v, u32* aH, u32* aL) {
    hilo(v[0], v[1], aH[0], aL[0]);
    hilo(v[2], v[3], aH[1], aL[1]);
    hilo(v[4], v[5], aH[2], aL[2]);
    hilo(v[6], v[7], aH[3], aL[3]);
}
// pack a single n8 C tile (4 floats) into A k-chunk positions [0],[1]; zero [2],[3]
__device__ __forceinline__ void packA4z(const float* c4, u32* aH, u32* aL) {
    hilo(c4[0], c4[1], aH[0], aL[0]);
    hilo(c4[2], c4[3], aH[1], aL[1]);
    aH[2] = 0u; aL[2] = 0u; aH[3] = 0u; aL[3] = 0u;
}

// split-accumulator stage: c (pre-init with bias) += A @ W (3-pass hi/lo)
template <int KC, int NT>
__device__ __forceinline__ void mstage(const u32* aH, const u32* aL,
                                       const uint4* wf, int lane, float c[][4]) {
    float cL[NT][4];
#pragma unroll
    for (int nt = 0; nt < NT; nt++)
#pragma unroll
        for (int i = 0; i < 4; i++) cL[nt][i] = 0.0f;
#pragma unroll
    for (int kc = 0; kc < KC; kc++) {
        u32 h0 = aH[kc * 4 + 0], h1 = aH[kc * 4 + 1];
        u32 h2 = aH[kc * 4 + 2], h3 = aH[kc * 4 + 3];
        u32 l0 = aL[kc * 4 + 0], l1 = aL[kc * 4 + 1];
        u32 l2 = aL[kc * 4 + 2], l3 = aL[kc * 4 + 3];
#pragma unroll
        for (int nt = 0; nt < NT; nt++) {
            uint4 w = wf[(kc * NT + nt) * 32 + lane];
            mma16816(c[nt], h0, h1, h2, h3, w.x, w.y);
            mma16816(cL[nt], l0, l1, l2, l3, w.x, w.y);
            mma16816(cL[nt], h0, h1, h2, h3, w.z, w.w);
        }
    }
#pragma unroll
    for (int nt = 0; nt < NT; nt++)
#pragma unroll
        for (int i = 0; i < 4; i++) c[nt][i] += cL[nt][i];
}

template <int NT>
__device__ __forceinline__ void binit(float c[][4], const float* sb, int qid) {
#pragma unroll
    for (int nt = 0; nt < NT; nt++) {
        float2 b = *reinterpret_cast<const float2*>(sb + nt * 8 + 2 * qid);
        c[nt][0] = b.x; c[nt][1] = b.y; c[nt][2] = b.x; c[nt][3] = b.y;
    }
}

// ---------------------------------------------------------------------------
// main kernel: warp = 32 trajectories, state in fragment layout, no smem
// roundtrips, no barriers inside the step loop.
// ---------------------------------------------------------------------------
__global__ void __launch_bounds__(CTA_THREADS, 3) sim_kernel(
    const float* __restrict__ dw, const float* __restrict__ X0,
    const float* __restrict__ A,  const float* __restrict__ Bm,
    const float* __restrict__ Cm, const float* __restrict__ Dm,
    const float* __restrict__ pW1, const float* __restrict__ pb1,
    const float* __restrict__ pW2, const float* __restrict__ pb2,
    const float* __restrict__ pW3, const float* __restrict__ pb3,
    const float* __restrict__ zW1, const float* __restrict__ zb1,
    const float* __restrict__ zW2, const float* __restrict__ zb2,
    const float* __restrict__ zW3, const float* __restrict__ zb3,
    const float* __restrict__ yW1, const float* __restrict__ yb1,
    const float* __restrict__ yW2, const float* __restrict__ yb2,
    const float* __restrict__ yW3, const float* __restrict__ yb3)
{
    // tiles: 0-1 P1 | 2-3 P2 | 4-5 P3 | 6-8 S1 | 9-14 S2 | 15-20 S3
    //        21-26 S4 | 27-34 S5
    __shared__ uint4 WF[35 * 32];      // 17.9 KB
    __shared__ float sbias[96];
    __shared__ float sb1[24], sw1[24];
    __shared__ float r0s[4], r1s[4];

    const int tid = threadIdx.x;
    const int wid = tid >> 5;
    const int lane = tid & 31;
    const int grp = lane >> 2, qid = lane & 3;

    // ---- bias tables ----
    for (int i = tid; i < 96; i += CTA_THREADS) {
        float b = 0.0f;
        if (i < 16)      { if (i < 10) b = yb1[i]; }
        else if (i < 32) { if (i - 16 < 10) b = yb2[i - 16]; }
        else if (i < 48) { b = yb3[i - 32]; }
        else if (i < 72) { int n = i - 48; b = (n < 10) ? zb2[n] : ((n < 20) ? pb2[n - 10] : 0.0f); }
        else             { int n = i - 72; b = (n < 16) ? zb3[n] : pb3[n - 16]; }
        sbias[i] = b;
    }
    if (tid < 24) {
        int n = tid;
        sb1[n] = (n < 10) ? zb1[n] : ((n < 20) ? pb1[n - 10] : 0.0f);
        sw1[n] = (n < 10) ? zW1[n] : ((n < 20) ? pW1[n - 10] : 0.0f);
    }

    // ---- weight fragment tables ----
    for (int idx = tid; idx < 35 * 32; idx += CTA_THREADS) {
        int tile = idx >> 5, ln = idx & 31;
        int stage, kc, nt;
        if      (tile < 2)  { stage = 0; kc = 0; nt = tile; }
        else if (tile < 4)  { stage = 1; kc = 0; nt = tile - 2; }
        else if (tile < 6)  { stage = 2; kc = 0; nt = tile - 4; }
        else if (tile < 9)  { stage = 3; kc = 0; nt = tile - 6; }
        else if (tile < 15) { int r = tile - 9;  stage = 4; kc = r / 3; nt = r % 3; }
        else if (tile < 21) { int r = tile - 15; stage = 5; kc = r / 3; nt = r % 3; }
        else if (tile < 27) { int r = tile - 21; stage = 6; kc = r / 3; nt = r % 3; }
        else                { int r = tile - 27; stage = 7; kc = r / 4; nt = r % 4; }
        int n = nt * 8 + (ln >> 2);
        int k0 = kc * 16 + (ln & 3) * 2;
        float w[4];
#pragma unroll
        for (int q = 0; q < 4; q++) {
            int k = k0 + (q & 1) + (q >> 1) * 8;
            float val = 0.0f;
            switch (stage) {
                case 0: if (k < 16 && n < 10) val = yW1[k * 10 + n]; break;
                case 1: if (k < 10 && n < 10) val = yW2[k * 10 + n]; break;
                case 2: if (k < 10 && n < 16) val = yW3[k * 16 + n]; break;
                case 3:
                    if (k < 16) {
                        if (n < 10)      val = zW1[(k + 1) * 10 + n];
                        else if (n < 20) val = pW1[(k + 1) * 10 + (n - 10)];
                    }
                    break;
                case 4:
                    if (n < 10 && k < 10) val = zW2[k * 10 + n];
                    else if (n >= 10 && n < 20 && k >= 10 && k < 20)
                        val = pW2[(k - 10) * 10 + (n - 10)];
                    break;
                case 5:
                    if (n < 16) { if (k < 10) val = zW3[k * 16 + n]; }
                    else if (k >= 10 && k < 20) val = pW3[(k - 10) * 8 + (n - 16)];
                    break;
                case 6:
                    if (k < 16) {
                        if (n < 16)      val = A[k * 16 + n];
                        else if (n < 24) val = Bm[k * 8 + (n - 16)];
                    } else {
                        if (n < 16)      val = Cm[(k - 16) * 16 + n];
                        else if (n < 24) val = Dm[(k - 16) * 8 + (n - 16)];
                    }
                    break;
                default:
                    if (k < 16) {
                        if (n < 16) val = A[n * 16 + k];
                        else        val = Cm[(n - 16) * 16 + k];
                    } else if (k < 24) {
                        if (n < 16) val = Bm[n * 8 + (k - 16)];
                        else        val = Dm[(n - 16) * 8 + (k - 16)];
                    }
                    break;
            }
            w[q] = val;
        }
        u32 h0, l0, h1, l1;
        hilo(w[0], w[1], h0, l0);
        hilo(w[2], w[3], h1, l1);
        WF[idx] = make_uint4(h0, h1, l0, l1);
    }
    __syncthreads();

    const int traj0 = blockIdx.x * CTA_THREADS + wid * 32;

    // per-thread S1 bias bases (cols 2q,2q+1, 8+2q,9+2q, 16+2q,17+2q)
    float s1b[6], s1w[6];
#pragma unroll
    for (int j = 0; j < 3; j++) {
        int col = j * 8 + 2 * qid;
        s1b[2 * j] = sb1[col];     s1b[2 * j + 1] = sb1[col + 1];
        s1w[2 * j] = sw1[col];     s1w[2 * j + 1] = sw1[col + 1];
    }

    // ---- state in fragment layout: Xf/Yf[mt*8 + tile*4 + {loc0,loc1,hic0,hic1}] ----
    float Xf[16], Yf[16];
#pragma unroll
    for (int mt = 0; mt < 2; mt++) {
        int rlo = traj0 + mt * 16 + grp;
#pragma unroll
        for (int tt = 0; tt < 2; tt++) {
            int col = tt * 8 + 2 * qid;
            float2 a = *reinterpret_cast<const float2*>(X0 + (size_t)rlo * 16 + col);
            float2 b = *reinterpret_cast<const float2*>(X0 + (size_t)(rlo + 8) * 16 + col);
            Xf[mt * 8 + tt * 4 + 0] = a.x; Xf[mt * 8 + tt * 4 + 1] = a.y;
            Xf[mt * 8 + tt * 4 + 2] = b.x; Xf[mt * 8 + tt * 4 + 3] = b.y;
        }
    }

    u32 aH[8], aL[8];

    // ---- prologue: Y = MLP_Y0(X0), fragment-resident ----
#pragma unroll
    for (int mt = 0; mt < 2; mt++) {
        float c[2][4];
        packA8(Xf + mt * 8, aH, aL);
        binit<2>(c, sbias + 0, qid);
        mstage<1, 2>(aH, aL, WF + 0 * 32, lane, c);
#pragma unroll
        for (int j = 0; j < 8; j++) (&c[0][0])[j] = tanh_hw((&c[0][0])[j]);
        packA8(&c[0][0], aH, aL);
        binit<2>(c, sbias + 16, qid);
        mstage<1, 2>(aH, aL, WF + 2 * 32, lane, c);
#pragma unroll
        for (int j = 0; j < 8; j++) (&c[0][0])[j] = tanh_hw((&c[0][0])[j]);
        packA8(&c[0][0], aH, aL);
        binit<2>(c, sbias + 32, qid);
        mstage<1, 2>(aH, aL, WF + 4 * 32, lane, c);
#pragma unroll
        for (int j = 0; j < 8; j++) Yf[mt * 8 + j] = (&c[0][0])[j];
    }

    float lc = 0.0f;

    for (int t = 0; t < T_STEPS; t++) {
        float tt = (float)t * DT_F;
        float wgt = (t == 0 || t == T_STEPS - 1) ? LC_SCALE : 2.0f * LC_SCALE;
        const float* dwt = dw + (size_t)t * BATCH + traj0;

#pragma unroll
        for (int mt = 0; mt < 2; mt++) {
            float* Xv = Xf + mt * 8;
            float* Yv = Yf + mt * 8;
            float dlo = __ldg(dwt + mt * 16 + grp);
            float dhi = __ldg(dwt + mt * 16 + 8 + grp);

            // ---- S1: [t,X] -> h (z|phi), N=24 ----
            float c1[3][4];
#pragma unroll
            for (int j = 0; j < 3; j++) {
                float b0 = fmaf(tt, s1w[2 * j], s1b[2 * j]);
                float b1 = fmaf(tt, s1w[2 * j + 1], s1b[2 * j + 1]);
                c1[j][0] = b0; c1[j][1] = b1; c1[j][2] = b0; c1[j][3] = b1;
            }
            packA8(Xv, aH, aL);
            mstage<1, 3>(aH, aL, WF + 6 * 32, lane, c1);
#pragma unroll
            for (int j = 0; j < 12; j++) (&c1[0][0])[j] = tanh_hw((&c1[0][0])[j]);

            // ---- S2 dense: K=20(pad32), N=24 ----
            float c2[3][4];
            packA8(&c1[0][0], aH, aL);
            packA4z(&c1[2][0], aH + 4, aL + 4);
            binit<3>(c2, sbias + 48, qid);
            mstage<2, 3>(aH, aL, WF + 9 * 32, lane, c2);
#pragma unroll
            for (int j = 0; j < 12; j++) (&c2[0][0])[j] = tanh_hw((&c2[0][0])[j]);

            // ---- S3 dense: -> Zv (tiles 0,1), u (tile 2) ----
            float c3[3][4];
            packA8(&c2[0][0], aH, aL);
            packA4z(&c2[2][0], aH + 4, aL + 4);
            binit<3>(c3, sbias + 72, qid);
            mstage<2, 3>(aH, aL, WF + 15 * 32, lane, c3);

            // ---- S4: [Y|Zv] -> oy (tiles 0,1 = Y@A+Zv@C; tile 2 = Y@B+Zv@D) ----
            float c4[3][4];
#pragma unroll
            for (int j = 0; j < 12; j++) (&c4[0][0])[j] = 0.0f;
            packA8(Yv, aH, aL);
            packA8(&c3[0][0], aH + 4, aL + 4);
            mstage<2, 3>(aH, aL, WF + 21 * 32, lane, c4);

            // ---- lc: dh = oy_u + u ----
            {
                float ss = 0.0f;
#pragma unroll
                for (int i = 0; i < 4; i++) {
                    float dh = c4[2][i] + c3[2][i];
                    ss = fmaf(dh, dh, ss);
                }
                lc = fmaf(wgt, ss, lc);
            }

            // ---- Y update (uses old X) ----
#pragma unroll
            for (int ttl = 0; ttl < 2; ttl++)
#pragma unroll
                for (int i = 0; i < 4; i++) {
                    int k = ttl * 4 + i;
                    float dwr = (i < 2) ? dlo : dhi;
                    Yv[k] = fmaf(dwr, c3[ttl][i],
                                 fmaf(-(c4[ttl][i] + Xv[k]), DT_F, Yv[k]));
                }

            // ---- S5: [X|u] -> drift (tiles 0,1) | diff (tiles 2,3) ----
            float c5[4][4];
#pragma unroll
            for (int j = 0; j < 8; j++)  (&c5[0][0])[j] = GAMMA_F;
#pragma unroll
            for (int j = 8; j < 16; j++) (&c5[0][0])[j] = SIGMA_F;
            packA8(Xv, aH, aL);
            packA4z(&c3[2][0], aH + 4, aL + 4);
            mstage<2, 4>(aH, aL, WF + 27 * 32, lane, c5);

            // ---- X update ----
#pragma unroll
            for (int ttl = 0; ttl < 2; ttl++)
#pragma unroll
                for (int i = 0; i < 4; i++) {
                    int k = ttl * 4 + i;
                    float dwr = (i < 2) ? dlo : dhi;
                    Xv[k] = fmaf(dwr, c5[2 + ttl][i],
                                 fmaf(c5[ttl][i], DT_F, Xv[k]));
                }
        }
    }

    float lb = 0.0f;
#pragma unroll
    for (int k = 0; k < 16; k++) {
        float d = Yf[k] - Xf[k];
        lb = fmaf(d, d, lb);
    }

    // ---- block reduction (4 warps) ----
#pragma unroll
    for (int off = 16; off; off >>= 1) {
        lb += __shfl_down_sync(0xffffffffu, lb, off);
        lc += __shfl_down_sync(0xffffffffu, lc, off);
    }
    if (lane == 0) { r0s[wid] = lb; r1s[wid] = lc; }
    __syncthreads();
    if (tid == 0) {
        g_p0[blockIdx.x] = (r0s[0] + r0s[1]) + (r0s[2] + r0s[3]);
        g_p1[blockIdx.x] = (r1s[0] + r1s[1]) + (r1s[2] + r1s[3]);
    }
}

// ---------------------------------------------------------------------------
// final reduction: NCTA (=256) partials -> 2 means
// ---------------------------------------------------------------------------
__global__ void __launch_bounds__(NCTA) finalize_kernel(float* __restrict__ out) {
    int tid = threadIdx.x;
    float a = g_p0[tid];
    float c = g_p1[tid];
#pragma unroll
    for (int o = 16; o; o >>= 1) {
        a += __shfl_down_sync(0xffffffffu, a, o);
        c += __shfl_down_sync(0xffffffffu, c, o);
    }
    __shared__ float sa[NCTA / 32], sc[NCTA / 32];
    int warp = tid >> 5, lane = tid & 31;
    if (lane == 0) { sa[warp] = a; sc[warp] = c; }
    __syncthreads();
    if (warp == 0) {
        a = (lane < NCTA / 32) ? sa[lane] : 0.0f;
        c = (lane < NCTA / 32) ? sc[lane] : 0.0f;
#pragma unroll
        for (int o = 4; o; o >>= 1) {
            a += __shfl_down_sync(0xffffffffu, a, o);
            c += __shfl_down_sync(0xffffffffu, c, o);
        }
        if (lane == 0) {
            out[0] = a * (1.0f / (float)BATCH);
            out[1] = c * (1.0f / (float)BATCH);
        }
    }
}

extern "C" void kernel_launch(void* const* d_in, const int* in_sizes, int n_in,
                              void* d_out, int out_size) {
    const float* dw  = (const float*)d_in[0];
    const float* X0  = (const float*)d_in[1];
    const float* A   = (const float*)d_in[2];
    const float* Bm  = (const float*)d_in[3];
    const float* Cm  = (const float*)d_in[4];
    const float* Dm  = (const float*)d_in[5];
    const float* pW1 = (const float*)d_in[6];
    const float* pb1 = (const float*)d_in[7];
    const float* pW2 = (const float*)d_in[8];
    const float* pb2 = (const float*)d_in[9];
    const float* pW3 = (const float*)d_in[10];
    const float* pb3 = (const float*)d_in[11];
    const float* zW1 = (const float*)d_in[12];
    const float* zb1 = (const float*)d_in[13];
    const float* zW2 = (const float*)d_in[14];
    const float* zb2 = (const float*)d_in[15];
    const float* zW3 = (const float*)d_in[16];
    const float* zb3 = (const float*)d_in[17];
    const float* yW1 = (const float*)d_in[18];
    const float* yb1 = (const float*)d_in[19];
    const float* yW2 = (const float*)d_in[20];
    const float* yb2 = (const float*)d_in[21];
    const float* yW3 = (const float*)d_in[22];
    const float* yb3 = (const float*)d_in[23];

    sim_kernel<<<NCTA, CTA_THREADS>>>(dw, X0, A, Bm, Cm, Dm,
                                      pW1, pb1, pW2, pb2, pW3, pb3,
                                      zW1, zb1, zW2, zb2, zW3, zb3,
                                      yW1, yb1, yW2, yb2, yW3, yb3);
    finalize_kernel<<<1, NCTA>>>((float*)d_out);
}

// round 16
// speedup vs baseline: 2.7806x; 1.3083x over previous
#include <cuda_runtime.h>
#include <cuda_bf16.h>
#include <cstdint>

using u32 = unsigned int;

#define T_STEPS 50
#define BATCH 32768
#define CTA_THREADS 128
#define NCTA (BATCH / CTA_THREADS)   // 256

#define DT_F 0.01f
#define GAMMA_F 0.1f
#define SIGMA_F 0.2f
#define LC_SCALE (0.5f * 0.01f * 0.25f)   // 0.5*DT*TAU^2

static __device__ float g_p0[NCTA];
static __device__ float g_p1[NCTA];

// ---------------------------------------------------------------------------
// helpers
// ---------------------------------------------------------------------------
__device__ __forceinline__ float tanh_hw(float x) {
    float r; asm("tanh.approx.f32 %0, %1;" : "=f"(r) : "f"(x)); return r;
}
__device__ __forceinline__ u32 cvt2(float lo, float hi) {
    u32 r; asm("cvt.rn.bf16x2.f32 %0, %1, %2;" : "=r"(r) : "f"(hi), "f"(lo)); return r;
}
__device__ __forceinline__ void hilo(float v0, float v1, u32& h, u32& l) {
    h = cvt2(v0, v1);
    float h0 = __uint_as_float(h << 16);
    float h1 = __uint_as_float(h & 0xFFFF0000u);
    l = cvt2(v0 - h0, v1 - h1);
}
__device__ __forceinline__ void mma16816(float* c, u32 a0, u32 a1, u32 a2, u32 a3,
                                         u32 b0, u32 b1) {
    asm volatile(
        "mma.sync.aligned.m16n8k16.row.col.f32.bf16.bf16.f32 "
        "{%0,%1,%2,%3}, {%4,%5,%6,%7}, {%8,%9}, {%0,%1,%2,%3};"
        : "+f"(c[0]), "+f"(c[1]), "+f"(c[2]), "+f"(c[3])
        : "r"(a0), "r"(a1), "r"(a2), "r"(a3), "r"(b0), "r"(b1));
}

// pack an 8-float frag vector (tile0 c0..c3, tile1 c0..c3) into one A k-chunk
__device__ __forceinline__ void packA8(const float* v, u32* aH, u32* aL) {
    hilo(v[0], v[1], aH[0], aL[0]);
    hilo(v[2], v[3], aH[1], aL[1]);
    hilo(v[4], v[5], aH[2], aL[2]);
    hilo(v[6], v[7], aH[3], aL[3]);
}
// pack a single n8 C tile (4 floats) into A k-chunk positions [0],[1]; zero [2],[3]
__device__ __forceinline__ void packA4z(const float* c4, u32* aH, u32* aL) {
    hilo(c4[0], c4[1], aH[0], aL[0]);
    hilo(c4[2], c4[3], aH[1], aL[1]);
    aH[2] = 0u; aL[2] = 0u; aH[3] = 0u; aL[3] = 0u;
}

// single-M16 stage (prologue only)
template <int KC, int NT>
__device__ __forceinline__ void mstage(const u32* aH, const u32* aL,
                                       const uint4* wf, int lane, float c[][4]) {
    float cL[NT][4];
#pragma unroll
    for (int nt = 0; nt < NT; nt++)
#pragma unroll
        for (int i = 0; i < 4; i++) cL[nt][i] = 0.0f;
#pragma unroll
    for (int kc = 0; kc < KC; kc++) {
#pragma unroll
        for (int nt = 0; nt < NT; nt++) {
            uint4 w = wf[(kc * NT + nt) * 32 + lane];
            mma16816(c[nt],  aH[kc*4], aH[kc*4+1], aH[kc*4+2], aH[kc*4+3], w.x, w.y);
            mma16816(cL[nt], aL[kc*4], aL[kc*4+1], aL[kc*4+2], aL[kc*4+3], w.x, w.y);
            mma16816(cL[nt], aH[kc*4], aH[kc*4+1], aH[kc*4+2], aH[kc*4+3], w.z, w.w);
        }
    }
#pragma unroll
    for (int nt = 0; nt < NT; nt++)
#pragma unroll
        for (int i = 0; i < 4; i++) c[nt][i] += cL[nt][i];
}

// fused M=32 stage: one weight load feeds both half-tiles (independent chains)
template <int KC, int NT>
__device__ __forceinline__ void mstage2(const u32* aH0, const u32* aL0,
                                        const u32* aH1, const u32* aL1,
                                        const uint4* wf, int lane,
                                        float c0[][4], float c1[][4]) {
    float d0[NT][4], d1[NT][4];
#pragma unroll
    for (int nt = 0; nt < NT; nt++)
#pragma unroll
        for (int i = 0; i < 4; i++) { d0[nt][i] = 0.0f; d1[nt][i] = 0.0f; }
#pragma unroll
    for (int kc = 0; kc < KC; kc++) {
#pragma unroll
        for (int nt = 0; nt < NT; nt++) {
            uint4 w = wf[(kc * NT + nt) * 32 + lane];
            mma16816(c0[nt], aH0[kc*4], aH0[kc*4+1], aH0[kc*4+2], aH0[kc*4+3], w.x, w.y);
            mma16816(c1[nt], aH1[kc*4], aH1[kc*4+1], aH1[kc*4+2], aH1[kc*4+3], w.x, w.y);
            mma16816(d0[nt], aL0[kc*4], aL0[kc*4+1], aL0[kc*4+2], aL0[kc*4+3], w.x, w.y);
            mma16816(d1[nt], aL1[kc*4], aL1[kc*4+1], aL1[kc*4+2], aL1[kc*4+3], w.x, w.y);
            mma16816(d0[nt], aH0[kc*4], aH0[kc*4+1], aH0[kc*4+2], aH0[kc*4+3], w.z, w.w);
            mma16816(d1[nt], aH1[kc*4], aH1[kc*4+1], aH1[kc*4+2], aH1[kc*4+3], w.z, w.w);
        }
    }
#pragma unroll
    for (int nt = 0; nt < NT; nt++)
#pragma unroll
        for (int i = 0; i < 4; i++) { c0[nt][i] += d0[nt][i]; c1[nt][i] += d1[nt][i]; }
}

template <int NT>
__device__ __forceinline__ void binit(float c[][4], const float* sb, int qid) {
#pragma unroll
    for (int nt = 0; nt < NT; nt++) {
        float2 b = *reinterpret_cast<const float2*>(sb + nt * 8 + 2 * qid);
        c[nt][0] = b.x; c[nt][1] = b.y; c[nt][2] = b.x; c[nt][3] = b.y;
    }
}

// ---------------------------------------------------------------------------
// main kernel
// ---------------------------------------------------------------------------
__global__ void __launch_bounds__(CTA_THREADS, 3) sim_kernel(
    const float* __restrict__ dw, const float* __restrict__ X0,
    const float* __restrict__ A,  const float* __restrict__ Bm,
    const float* __restrict__ Cm, const float* __restrict__ Dm,
    const float* __restrict__ pW1, const float* __restrict__ pb1,
    const float* __restrict__ pW2, const float* __restrict__ pb2,
    const float* __restrict__ pW3, const float* __restrict__ pb3,
    const float* __restrict__ zW1, const float* __restrict__ zb1,
    const float* __restrict__ zW2, const float* __restrict__ zb2,
    const float* __restrict__ zW3, const float* __restrict__ zb3,
    const float* __restrict__ yW1, const float* __restrict__ yb1,
    const float* __restrict__ yW2, const float* __restrict__ yb2,
    const float* __restrict__ yW3, const float* __restrict__ yb3)
{
    // tiles: 0-1 P1 | 2-3 P2 | 4-5 P3 | 6-8 S1 | 9-14 S2 | 15-20 S3
    //        21-26 S4 | 27-34 S5
    __shared__ uint4 WF[35 * 32];      // 17.9 KB
    __shared__ float sbias[96];
    __shared__ float sb1[24], sw1[24];
    __shared__ float r0s[4], r1s[4];

    const int tid = threadIdx.x;
    const int wid = tid >> 5;
    const int lane = tid & 31;
    const int grp = lane >> 2, qid = lane & 3;

    // ---- bias tables ----
    for (int i = tid; i < 96; i += CTA_THREADS) {
        float b = 0.0f;
        if (i < 16)      { if (i < 10) b = yb1[i]; }
        else if (i < 32) { if (i - 16 < 10) b = yb2[i - 16]; }
        else if (i < 48) { b = yb3[i - 32]; }
        else if (i < 72) { int n = i - 48; b = (n < 10) ? zb2[n] : ((n < 20) ? pb2[n - 10] : 0.0f); }
        else             { int n = i - 72; b = (n < 16) ? zb3[n] : pb3[n - 16]; }
        sbias[i] = b;
    }
    if (tid < 24) {
        int n = tid;
        sb1[n] = (n < 10) ? zb1[n] : ((n < 20) ? pb1[n - 10] : 0.0f);
        sw1[n] = (n < 10) ? zW1[n] : ((n < 20) ? pW1[n - 10] : 0.0f);
    }

    // ---- weight fragment tables (identical to R15) ----
    for (int idx = tid; idx < 35 * 32; idx += CTA_THREADS) {
        int tile = idx >> 5, ln = idx & 31;
        int stage, kc, nt;
        if      (tile < 2)  { stage = 0; kc = 0; nt = tile; }
        else if (tile < 4)  { stage = 1; kc = 0; nt = tile - 2; }
        else if (tile < 6)  { stage = 2; kc = 0; nt = tile - 4; }
        else if (tile < 9)  { stage = 3; kc = 0; nt = tile - 6; }
        else if (tile < 15) { int r = tile - 9;  stage = 4; kc = r / 3; nt = r % 3; }
        else if (tile < 21) { int r = tile - 15; stage = 5; kc = r / 3; nt = r % 3; }
        else if (tile < 27) { int r = tile - 21; stage = 6; kc = r / 3; nt = r % 3; }
        else                { int r = tile - 27; stage = 7; kc = r / 4; nt = r % 4; }
        int n = nt * 8 + (ln >> 2);
        int k0 = kc * 16 + (ln & 3) * 2;
        float w[4];
#pragma unroll
        for (int q = 0; q < 4; q++) {
            int k = k0 + (q & 1) + (q >> 1) * 8;
            float val = 0.0f;
            switch (stage) {
                case 0: if (k < 16 && n < 10) val = yW1[k * 10 + n]; break;
                case 1: if (k < 10 && n < 10) val = yW2[k * 10 + n]; break;
                case 2: if (k < 10 && n < 16) val = yW3[k * 16 + n]; break;
                case 3:
                    if (k < 16) {
                        if (n < 10)      val = zW1[(k + 1) * 10 + n];
                        else if (n < 20) val = pW1[(k + 1) * 10 + (n - 10)];
                    }
                    break;
                case 4:
                    if (n < 10 && k < 10) val = zW2[k * 10 + n];
                    else if (n >= 10 && n < 20 && k >= 10 && k < 20)
                        val = pW2[(k - 10) * 10 + (n - 10)];
                    break;
                case 5:
                    if (n < 16) { if (k < 10) val = zW3[k * 16 + n]; }
                    else if (k >= 10 && k < 20) val = pW3[(k - 10) * 8 + (n - 16)];
                    break;
                case 6:
                    if (k < 16) {
                        if (n < 16)      val = A[k * 16 + n];
                        else if (n < 24) val = Bm[k * 8 + (n - 16)];
                    } else {
                        if (n < 16)      val = Cm[(k - 16) * 16 + n];
                        else if (n < 24) val = Dm[(k - 16) * 8 + (n - 16)];
                    }
                    break;
                default:
                    if (k < 16) {
                        if (n < 16) val = A[n * 16 + k];
                        else        val = Cm[(n - 16) * 16 + k];
                    } else if (k < 24) {
                        if (n < 16) val = Bm[n * 8 + (k - 16)];
                        else        val = Dm[(n - 16) * 8 + (k - 16)];
                    }
                    break;
            }
            w[q] = val;
        }
        u32 h0, l0, h1, l1;
        hilo(w[0], w[1], h0, l0);
        hilo(w[2], w[3], h1, l1);
        WF[idx] = make_uint4(h0, h1, l0, l1);
    }
    __syncthreads();

    const int traj0 = blockIdx.x * CTA_THREADS + wid * 32;

    // per-thread S1 bias bases (cols 2q,2q+1 within each n8 tile)
    float s1b[6], s1w[6];
#pragma unroll
    for (int j = 0; j < 3; j++) {
        int col = j * 8 + 2 * qid;
        s1b[2 * j] = sb1[col];     s1b[2 * j + 1] = sb1[col + 1];
        s1w[2 * j] = sw1[col];     s1w[2 * j + 1] = sw1[col + 1];
    }

    // ---- state in fragment layout ----
    float Xf[16], Yf[16];
#pragma unroll
    for (int mt = 0; mt < 2; mt++) {
        int rlo = traj0 + mt * 16 + grp;
#pragma unroll
        for (int tt = 0; tt < 2; tt++) {
            int col = tt * 8 + 2 * qid;
            float2 a = *reinterpret_cast<const float2*>(X0 + (size_t)rlo * 16 + col);
            float2 b = *reinterpret_cast<const float2*>(X0 + (size_t)(rlo + 8) * 16 + col);
            Xf[mt * 8 + tt * 4 + 0] = a.x; Xf[mt * 8 + tt * 4 + 1] = a.y;
            Xf[mt * 8 + tt * 4 + 2] = b.x; Xf[mt * 8 + tt * 4 + 3] = b.y;
        }
    }

    // ---- prologue: Y = MLP_Y0(X0) (M16 path, one-time) ----
#pragma unroll
    for (int mt = 0; mt < 2; mt++) {
        u32 aH[4], aL[4];
        float c[2][4];
        packA8(Xf + mt * 8, aH, aL);
        binit<2>(c, sbias + 0, qid);
        mstage<1, 2>(aH, aL, WF + 0 * 32, lane, c);
#pragma unroll
        for (int j = 0; j < 8; j++) (&c[0][0])[j] = tanh_hw((&c[0][0])[j]);
        packA8(&c[0][0], aH, aL);
        binit<2>(c, sbias + 16, qid);
        mstage<1, 2>(aH, aL, WF + 2 * 32, lane, c);
#pragma unroll
        for (int j = 0; j < 8; j++) (&c[0][0])[j] = tanh_hw((&c[0][0])[j]);
        packA8(&c[0][0], aH, aL);
        binit<2>(c, sbias + 32, qid);
        mstage<1, 2>(aH, aL, WF + 4 * 32, lane, c);
#pragma unroll
        for (int j = 0; j < 8; j++) Yf[mt * 8 + j] = (&c[0][0])[j];
    }

    float lc = 0.0f;

    for (int t = 0; t < T_STEPS; t++) {
        float tt = (float)t * DT_F;
        float wgt = (t == 0 || t == T_STEPS - 1) ? LC_SCALE : 2.0f * LC_SCALE;
        const float* dwt = dw + (size_t)t * BATCH + traj0;

        float dlo0 = __ldg(dwt + grp),      dhi0 = __ldg(dwt + 8 + grp);
        float dlo1 = __ldg(dwt + 16 + grp), dhi1 = __ldg(dwt + 24 + grp);

        // pack X once (reused by S1 and S5)
        u32 xH0[4], xL0[4], xH1[4], xL1[4];
        packA8(Xf, xH0, xL0);
        packA8(Xf + 8, xH1, xL1);

        // ---- S1: [t,X] -> h (z|phi) ----
        float c1a[3][4], c1b[3][4];
#pragma unroll
        for (int j = 0; j < 3; j++) {
            float b0 = fmaf(tt, s1w[2 * j], s1b[2 * j]);
            float b1 = fmaf(tt, s1w[2 * j + 1], s1b[2 * j + 1]);
            c1a[j][0] = b0; c1a[j][1] = b1; c1a[j][2] = b0; c1a[j][3] = b1;
            c1b[j][0] = b0; c1b[j][1] = b1; c1b[j][2] = b0; c1b[j][3] = b1;
        }
        mstage2<1, 3>(xH0, xL0, xH1, xL1, WF + 6 * 32, lane, c1a, c1b);
#pragma unroll
        for (int j = 0; j < 12; j++) {
            (&c1a[0][0])[j] = tanh_hw((&c1a[0][0])[j]);
            (&c1b[0][0])[j] = tanh_hw((&c1b[0][0])[j]);
        }

        // ---- S2 dense: K=20(pad32), N=24 ----
        u32 aH0[8], aL0[8], aH1[8], aL1[8];
        packA8(&c1a[0][0], aH0, aL0);  packA4z(&c1a[2][0], aH0 + 4, aL0 + 4);
        packA8(&c1b[0][0], aH1, aL1);  packA4z(&c1b[2][0], aH1 + 4, aL1 + 4);
        float c2a[3][4], c2b[3][4];
        binit<3>(c2a, sbias + 48, qid);
        binit<3>(c2b, sbias + 48, qid);
        mstage2<2, 3>(aH0, aL0, aH1, aL1, WF + 9 * 32, lane, c2a, c2b);
#pragma unroll
        for (int j = 0; j < 12; j++) {
            (&c2a[0][0])[j] = tanh_hw((&c2a[0][0])[j]);
            (&c2b[0][0])[j] = tanh_hw((&c2b[0][0])[j]);
        }

        // ---- S3 dense: -> Zv (tiles 0,1), u (tile 2) ----
        packA8(&c2a[0][0], aH0, aL0);  packA4z(&c2a[2][0], aH0 + 4, aL0 + 4);
        packA8(&c2b[0][0], aH1, aL1);  packA4z(&c2b[2][0], aH1 + 4, aL1 + 4);
        float c3a[3][4], c3b[3][4];
        binit<3>(c3a, sbias + 72, qid);
        binit<3>(c3b, sbias + 72, qid);
        mstage2<2, 3>(aH0, aL0, aH1, aL1, WF + 15 * 32, lane, c3a, c3b);

        // ---- S4: [Y|Zv] -> oy ----
        packA8(Yf, aH0, aL0);      packA8(&c3a[0][0], aH0 + 4, aL0 + 4);
        packA8(Yf + 8, aH1, aL1);  packA8(&c3b[0][0], aH1 + 4, aL1 + 4);
        float c4a[3][4], c4b[3][4];
#pragma unroll
        for (int j = 0; j < 12; j++) { (&c4a[0][0])[j] = 0.0f; (&c4b[0][0])[j] = 0.0f; }
        mstage2<2, 3>(aH0, aL0, aH1, aL1, WF + 21 * 32, lane, c4a, c4b);

        // ---- lc ----
        {
            float ss0 = 0.0f, ss1 = 0.0f;
#pragma unroll
            for (int i = 0; i < 4; i++) {
                float dh0 = c4a[2][i] + c3a[2][i];
                float dh1 = c4b[2][i] + c3b[2][i];
                ss0 = fmaf(dh0, dh0, ss0);
                ss1 = fmaf(dh1, dh1, ss1);
            }
            lc = fmaf(wgt, ss0 + ss1, lc);
        }

        // ---- Y update (uses old X) ----
#pragma unroll
        for (int ttl = 0; ttl < 2; ttl++)
#pragma unroll
            for (int i = 0; i < 4; i++) {
                int k = ttl * 4 + i;
                float d0 = (i < 2) ? dlo0 : dhi0;
                float d1 = (i < 2) ? dlo1 : dhi1;
                Yf[k]     = fmaf(d0, c3a[ttl][i], fmaf(-(c4a[ttl][i] + Xf[k]), DT_F, Yf[k]));
                Yf[8 + k] = fmaf(d1, c3b[ttl][i], fmaf(-(c4b[ttl][i] + Xf[8 + k]), DT_F, Yf[8 + k]));
            }

        // ---- S5: [X|u] -> drift (tiles 0,1) | diff (tiles 2,3) ----
#pragma unroll
        for (int i = 0; i < 4; i++) {
            aH0[i] = xH0[i]; aL0[i] = xL0[i];
            aH1[i] = xH1[i]; aL1[i] = xL1[i];
        }
        packA4z(&c3a[2][0], aH0 + 4, aL0 + 4);
        packA4z(&c3b[2][0], aH1 + 4, aL1 + 4);
        float c5a[4][4], c5b[4][4];
#pragma unroll
        for (int j = 0; j < 8; j++)  { (&c5a[0][0])[j] = GAMMA_F; (&c5b[0][0])[j] = GAMMA_F; }
#pragma unroll
        for (int j = 8; j < 16; j++) { (&c5a[0][0])[j] = SIGMA_F; (&c5b[0][0])[j] = SIGMA_F; }
        mstage2<2, 4>(aH0, aL0, aH1, aL1, WF + 27 * 32, lane, c5a, c5b);

        // ---- X update ----
#pragma unroll
        for (int ttl = 0; ttl < 2; ttl++)
#pragma unroll
            for (int i = 0; i < 4; i++) {
                int k = ttl * 4 + i;
                float d0 = (i < 2) ? dlo0 : dhi0;
                float d1 = (i < 2) ? dlo1 : dhi1;
                Xf[k]     = fmaf(d0, c5a[2 + ttl][i], fmaf(c5a[ttl][i], DT_F, Xf[k]));
                Xf[8 + k] = fmaf(d1, c5b[2 + ttl][i], fmaf(c5b[ttl][i], DT_F, Xf[8 + k]));
            }
    }

    float lb = 0.0f;
#pragma unroll
    for (int k = 0; k < 16; k++) {
        float d = Yf[k] - Xf[k];
        lb = fmaf(d, d, lb);
    }

    // ---- block reduction (4 warps) ----
#pragma unroll
    for (int off = 16; off; off >>= 1) {
        lb += __shfl_down_sync(0xffffffffu, lb, off);
        lc += __shfl_down_sync(0xffffffffu, lc, off);
    }
    if (lane == 0) { r0s[wid] = lb; r1s[wid] = lc; }
    __syncthreads();
    if (tid == 0) {
        g_p0[blockIdx.x] = (r0s[0] + r0s[1]) + (r0s[2] + r0s[3]);
        g_p1[blockIdx.x] = (r1s[0] + r1s[1]) + (r1s[2] + r1s[3]);
    }
}

// ---------------------------------------------------------------------------
// final reduction: NCTA (=256) partials -> 2 means
// ---------------------------------------------------------------------------
__global__ void __launch_bounds__(NCTA) finalize_kernel(float* __restrict__ out) {
    int tid = threadIdx.x;
    float a = g_p0[tid];
    float c = g_p1[tid];
#pragma unroll
    for (int o = 16; o; o >>= 1) {
        a += __shfl_down_sync(0xffffffffu, a, o);
        c += __shfl_down_sync(0xffffffffu, c, o);
    }
    __shared__ float sa[NCTA / 32], sc[NCTA / 32];
    int warp = tid >> 5, lane = tid & 31;
    if (lane == 0) { sa[warp] = a; sc[warp] = c; }
    __syncthreads();
    if (warp == 0) {
        a = (lane < NCTA / 32) ? sa[lane] : 0.0f;
        c = (lane < NCTA / 32) ? sc[lane] : 0.0f;
#pragma unroll
        for (int o = 4; o; o >>= 1) {
            a += __shfl_down_sync(0xffffffffu, a, o);
            c += __shfl_down_sync(0xffffffffu, c, o);
        }
        if (lane == 0) {
            out[0] = a * (1.0f / (float)BATCH);
            out[1] = c * (1.0f / (float)BATCH);
        }
    }
}

extern "C" void kernel_launch(void* const* d_in, const int* in_sizes, int n_in,
                              void* d_out, int out_size) {
    const float* dw  = (const float*)d_in[0];
    const float* X0  = (const float*)d_in[1];
    const float* A   = (const float*)d_in[2];
    const float* Bm  = (const float*)d_in[3];
    const float* Cm  = (const float*)d_in[4];
    const float* Dm  = (const float*)d_in[5];
    const float* pW1 = (const float*)d_in[6];
    const float* pb1 = (const float*)d_in[7];
    const float* pW2 = (const float*)d_in[8];
    const float* pb2 = (const float*)d_in[9];
    const float* pW3 = (const float*)d_in[10];
    const float* pb3 = (const float*)d_in[11];
    const float* zW1 = (const float*)d_in[12];
    const float* zb1 = (const float*)d_in[13];
    const float* zW2 = (const float*)d_in[14];
    const float* zb2 = (const float*)d_in[15];
    const float* zW3 = (const float*)d_in[16];
    const float* zb3 = (const float*)d_in[17];
    const float* yW1 = (const float*)d_in[18];
    const float* yb1 = (const float*)d_in[19];
    const float* yW2 = (const float*)d_in[20];
    const float* yb2 = (const float*)d_in[21];
    const float* yW3 = (const float*)d_in[22];
    const float* yb3 = (const float*)d_in[23];

    sim_kernel<<<NCTA, CTA_THREADS>>>(dw, X0, A, Bm, Cm, Dm,
                                      pW1, pb1, pW2, pb2, pW3, pb3,
                                      zW1, zb1, zW2, zb2, zW3, zb3,
                                      yW1, yb1, yW2, yb2, yW3, yb3);
    finalize_kernel<<<1, NCTA>>>((float*)d_out);
}

// round 17
// speedup vs baseline: 4.5801x; 1.6472x over previous
#include <cuda_runtime.h>
#include <cuda_bf16.h>
#include <cstdint>

using u32 = unsigned int;

#define T_STEPS 50
#define BATCH 32768
#define CTA_THREADS 128
#define NCTA (BATCH / CTA_THREADS)   // 256

#define DT_F 0.01f
#define GAMMA_F 0.1f
#define SIGMA_F 0.2f
#define LC_SCALE (0.5f * 0.01f * 0.25f)   // 0.5*DT*TAU^2

static __device__ float g_p0[NCTA];
static __device__ float g_p1[NCTA];

// ---------------------------------------------------------------------------
// helpers
// ---------------------------------------------------------------------------
__device__ __forceinline__ float tanh_hw(float x) {
    float r; asm("tanh.approx.f32 %0, %1;" : "=f"(r) : "f"(x)); return r;
}
__device__ __forceinline__ u32 totf(float x) {
    u32 r; asm("cvt.rna.tf32.f32 %0, %1;" : "=r"(r) : "f"(x)); return r;
}
// tf32 m16n8k8 MMA, fp32 accum in place
__device__ __forceinline__ void mmatf(float* c, u32 a0, u32 a1, u32 a2, u32 a3,
                                      u32 b0, u32 b1) {
    asm volatile(
        "mma.sync.aligned.m16n8k8.row.col.f32.tf32.tf32.f32 "
        "{%0,%1,%2,%3}, {%4,%5,%6,%7}, {%8,%9}, {%0,%1,%2,%3};"
        : "+f"(c[0]), "+f"(c[1]), "+f"(c[2]), "+f"(c[3])
        : "r"(a0), "r"(a1), "r"(a2), "r"(a3), "r"(b0), "r"(b1));
}

// Convert one C n8-tile (c0,c1,c2,c3) into one A k8-chunk.
// With K-permuted weights (b0<-W[2q][n], b1<-W[2q+1][n]), the A fragment is
// (a0,a1,a2,a3) = (c0, c2, c1, c3) — register-resident chaining, no shuffles.
__device__ __forceinline__ void cvtT(const float* v, u32* a) {
    a[0] = totf(v[0]); a[1] = totf(v[2]); a[2] = totf(v[1]); a[3] = totf(v[3]);
}

// fused M=32 stage: one weight load feeds both half-tiles
template <int KC, int NT>
__device__ __forceinline__ void tstage2(const u32* a0, const u32* a1,
                                        const uint2* wf, int lane,
                                        float c0[][4], float c1[][4]) {
#pragma unroll
    for (int kc = 0; kc < KC; kc++) {
#pragma unroll
        for (int nt = 0; nt < NT; nt++) {
            uint2 w = wf[(kc * NT + nt) * 32 + lane];
            mmatf(c0[nt], a0[kc*4], a0[kc*4+1], a0[kc*4+2], a0[kc*4+3], w.x, w.y);
            mmatf(c1[nt], a1[kc*4], a1[kc*4+1], a1[kc*4+2], a1[kc*4+3], w.x, w.y);
        }
    }
}
// single-half stage (prologue)
template <int KC, int NT>
__device__ __forceinline__ void tstage(const u32* a, const uint2* wf, int lane,
                                       float c[][4]) {
#pragma unroll
    for (int kc = 0; kc < KC; kc++)
#pragma unroll
        for (int nt = 0; nt < NT; nt++) {
            uint2 w = wf[(kc * NT + nt) * 32 + lane];
            mmatf(c[nt], a[kc*4], a[kc*4+1], a[kc*4+2], a[kc*4+3], w.x, w.y);
        }
}

template <int NT>
__device__ __forceinline__ void binit(float c[][4], const float* sb, int qid) {
#pragma unroll
    for (int nt = 0; nt < NT; nt++) {
        float2 b = *reinterpret_cast<const float2*>(sb + nt * 8 + 2 * qid);
        c[nt][0] = b.x; c[nt][1] = b.y; c[nt][2] = b.x; c[nt][3] = b.y;
    }
}

// ---------------------------------------------------------------------------
// main kernel
// ---------------------------------------------------------------------------
__global__ void __launch_bounds__(CTA_THREADS, 3) sim_kernel(
    const float* __restrict__ dw, const float* __restrict__ X0,
    const float* __restrict__ A,  const float* __restrict__ Bm,
    const float* __restrict__ Cm, const float* __restrict__ Dm,
    const float* __restrict__ pW1, const float* __restrict__ pb1,
    const float* __restrict__ pW2, const float* __restrict__ pb2,
    const float* __restrict__ pW3, const float* __restrict__ pb3,
    const float* __restrict__ zW1, const float* __restrict__ zb1,
    const float* __restrict__ zW2, const float* __restrict__ zb2,
    const float* __restrict__ zW3, const float* __restrict__ zb3,
    const float* __restrict__ yW1, const float* __restrict__ yb1,
    const float* __restrict__ yW2, const float* __restrict__ yb2,
    const float* __restrict__ yW3, const float* __restrict__ yb3)
{
    // weight units (k8chunk x n8tile), order (kc*NT+nt):
    // P1@0(4) P2@4(4) P3@8(4) S1@12(6) S2@18(9) S3@27(9) S4@36(12) S5@48(12)
    __shared__ uint2 TW[60 * 32];      // 15.4 KB
    __shared__ float sbias[96];
    __shared__ float sb1[24], sw1[24];
    __shared__ float r0s[4], r1s[4];

    const int tid = threadIdx.x;
    const int wid = tid >> 5;
    const int lane = tid & 31;
    const int grp = lane >> 2, qid = lane & 3;

    // ---- bias tables ----
    for (int i = tid; i < 96; i += CTA_THREADS) {
        float b = 0.0f;
        if (i < 16)      { if (i < 10) b = yb1[i]; }
        else if (i < 32) { if (i - 16 < 10) b = yb2[i - 16]; }
        else if (i < 48) { b = yb3[i - 32]; }
        else if (i < 72) { int n = i - 48; b = (n < 10) ? zb2[n] : ((n < 20) ? pb2[n - 10] : 0.0f); }
        else             { int n = i - 72; b = (n < 16) ? zb3[n] : pb3[n - 16]; }
        sbias[i] = b;
    }
    if (tid < 24) {
        int n = tid;
        sb1[n] = (n < 10) ? zb1[n] : ((n < 20) ? pb1[n - 10] : 0.0f);
        sw1[n] = (n < 10) ? zW1[n] : ((n < 20) ? pW1[n - 10] : 0.0f);
    }

    // ---- weight fragment tables (K-permuted: b0<-W[2q][n], b1<-W[2q+1][n]) ----
    for (int idx = tid; idx < 60 * 32; idx += CTA_THREADS) {
        int unit = idx >> 5, ln = idx & 31;
        int stage, kc, nt;
        if      (unit < 4)  { stage = 0; kc = unit >> 1;        nt = unit & 1; }
        else if (unit < 8)  { stage = 1; int r = unit - 4;  kc = r >> 1; nt = r & 1; }
        else if (unit < 12) { stage = 2; int r = unit - 8;  kc = r >> 1; nt = r & 1; }
        else if (unit < 18) { stage = 3; int r = unit - 12; kc = r / 3;  nt = r % 3; }
        else if (unit < 27) { stage = 4; int r = unit - 18; kc = r / 3;  nt = r % 3; }
        else if (unit < 36) { stage = 5; int r = unit - 27; kc = r / 3;  nt = r % 3; }
        else if (unit < 48) { stage = 6; int r = unit - 36; kc = r / 3;  nt = r % 3; }
        else                { stage = 7; int r = unit - 48; kc = r >> 2; nt = r & 3; }
        int g = ln >> 2, q = ln & 3;
        int n = nt * 8 + g;
        float wv[2];
#pragma unroll
        for (int s = 0; s < 2; s++) {
            int k = kc * 8 + 2 * q + s;
            float val = 0.0f;
            switch (stage) {
                case 0: if (k < 16 && n < 10) val = yW1[k * 10 + n]; break;
                case 1: if (k < 10 && n < 10) val = yW2[k * 10 + n]; break;
                case 2: if (k < 10 && n < 16) val = yW3[k * 16 + n]; break;
                case 3:
                    if (k < 16) {
                        if (n < 10)      val = zW1[(k + 1) * 10 + n];
                        else if (n < 20) val = pW1[(k + 1) * 10 + (n - 10)];
                    }
                    break;
                case 4:
                    if (n < 10 && k < 10) val = zW2[k * 10 + n];
                    else if (n >= 10 && n < 20 && k >= 10 && k < 20)
                        val = pW2[(k - 10) * 10 + (n - 10)];
                    break;
                case 5:
                    if (n < 16) { if (k < 10) val = zW3[k * 16 + n]; }
                    else if (k >= 10 && k < 20) val = pW3[(k - 10) * 8 + (n - 16)];
                    break;
                case 6:
                    if (k < 16) {
                        if (n < 16)      val = A[k * 16 + n];
                        else if (n < 24) val = Bm[k * 8 + (n - 16)];
                    } else {
                        if (n < 16)      val = Cm[(k - 16) * 16 + n];
                        else if (n < 24) val = Dm[(k - 16) * 8 + (n - 16)];
                    }
                    break;
                default:
                    if (k < 16) {
                        if (n < 16) val = A[n * 16 + k];
                        else        val = Cm[(n - 16) * 16 + k];
                    } else if (k < 24) {
                        if (n < 16) val = Bm[n * 8 + (k - 16)];
                        else        val = Dm[(n - 16) * 8 + (k - 16)];
                    }
                    break;
            }
            wv[s] = val;
        }
        TW[idx] = make_uint2(totf(wv[0]), totf(wv[1]));
    }
    __syncthreads();

    const int traj0 = blockIdx.x * CTA_THREADS + wid * 32;

    float s1b[6], s1w[6];
#pragma unroll
    for (int j = 0; j < 3; j++) {
        int col = j * 8 + 2 * qid;
        s1b[2 * j] = sb1[col];     s1b[2 * j + 1] = sb1[col + 1];
        s1w[2 * j] = sw1[col];     s1w[2 * j + 1] = sw1[col + 1];
    }

    // ---- state in fragment layout: tile order (c0,c1,c2,c3) ----
    float Xf[16], Yf[16];
#pragma unroll
    for (int mt = 0; mt < 2; mt++) {
        int rlo = traj0 + mt * 16 + grp;
#pragma unroll
        for (int tt = 0; tt < 2; tt++) {
            int col = tt * 8 + 2 * qid;
            float2 a = *reinterpret_cast<const float2*>(X0 + (size_t)rlo * 16 + col);
            float2 b = *reinterpret_cast<const float2*>(X0 + (size_t)(rlo + 8) * 16 + col);
            Xf[mt * 8 + tt * 4 + 0] = a.x; Xf[mt * 8 + tt * 4 + 1] = a.y;
            Xf[mt * 8 + tt * 4 + 2] = b.x; Xf[mt * 8 + tt * 4 + 3] = b.y;
        }
    }

    // ---- prologue: Y = MLP_Y0(X0) ----
#pragma unroll
    for (int mt = 0; mt < 2; mt++) {
        u32 a[8];
        float c[2][4];
        cvtT(Xf + mt * 8, a); cvtT(Xf + mt * 8 + 4, a + 4);
        binit<2>(c, sbias + 0, qid);
        tstage<2, 2>(a, TW + 0, lane, c);
#pragma unroll
        for (int j = 0; j < 8; j++) (&c[0][0])[j] = tanh_hw((&c[0][0])[j]);
        cvtT(&c[0][0], a); cvtT(&c[1][0], a + 4);
        binit<2>(c, sbias + 16, qid);
        tstage<2, 2>(a, TW + 4 * 32, lane, c);
#pragma unroll
        for (int j = 0; j < 8; j++) (&c[0][0])[j] = tanh_hw((&c[0][0])[j]);
        cvtT(&c[0][0], a); cvtT(&c[1][0], a + 4);
        binit<2>(c, sbias + 32, qid);
        tstage<2, 2>(a, TW + 8 * 32, lane, c);
#pragma unroll
        for (int j = 0; j < 8; j++) Yf[mt * 8 + j] = (&c[0][0])[j];
    }

    float lc = 0.0f;

    for (int t = 0; t < T_STEPS; t++) {
        float tt = (float)t * DT_F;
        float wgt = (t == 0 || t == T_STEPS - 1) ? LC_SCALE : 2.0f * LC_SCALE;
        const float* dwt = dw + (size_t)t * BATCH + traj0;

        float dlo0 = __ldg(dwt + grp),      dhi0 = __ldg(dwt + 8 + grp);
        float dlo1 = __ldg(dwt + 16 + grp), dhi1 = __ldg(dwt + 24 + grp);

        // cvt X once (S1 + S5)
        u32 xa0[8], xa1[8];
        cvtT(Xf, xa0);     cvtT(Xf + 4, xa0 + 4);
        cvtT(Xf + 8, xa1); cvtT(Xf + 12, xa1 + 4);

        // ---- S1: [t,X] -> h (z|phi), K=16, N=24 ----
        float c1a[3][4], c1b[3][4];
#pragma unroll
        for (int j = 0; j < 3; j++) {
            float b0 = fmaf(tt, s1w[2 * j], s1b[2 * j]);
            float b1 = fmaf(tt, s1w[2 * j + 1], s1b[2 * j + 1]);
            c1a[j][0] = b0; c1a[j][1] = b1; c1a[j][2] = b0; c1a[j][3] = b1;
            c1b[j][0] = b0; c1b[j][1] = b1; c1b[j][2] = b0; c1b[j][3] = b1;
        }
        tstage2<2, 3>(xa0, xa1, TW + 12 * 32, lane, c1a, c1b);
#pragma unroll
        for (int j = 0; j < 12; j++) {
            (&c1a[0][0])[j] = tanh_hw((&c1a[0][0])[j]);
            (&c1b[0][0])[j] = tanh_hw((&c1b[0][0])[j]);
        }

        // ---- S2: K=24 (20 + zero pad), N=24 ----
        u32 a0[12], a1[12];
        cvtT(&c1a[0][0], a0); cvtT(&c1a[1][0], a0 + 4); cvtT(&c1a[2][0], a0 + 8);
        cvtT(&c1b[0][0], a1); cvtT(&c1b[1][0], a1 + 4); cvtT(&c1b[2][0], a1 + 8);
        float c2a[3][4], c2b[3][4];
        binit<3>(c2a, sbias + 48, qid);
        binit<3>(c2b, sbias + 48, qid);
        tstage2<3, 3>(a0, a1, TW + 18 * 32, lane, c2a, c2b);
#pragma unroll
        for (int j = 0; j < 12; j++) {
            (&c2a[0][0])[j] = tanh_hw((&c2a[0][0])[j]);
            (&c2b[0][0])[j] = tanh_hw((&c2b[0][0])[j]);
        }

        // ---- S3: -> Zv (tiles 0,1), u (tile 2) ----
        cvtT(&c2a[0][0], a0); cvtT(&c2a[1][0], a0 + 4); cvtT(&c2a[2][0], a0 + 8);
        cvtT(&c2b[0][0], a1); cvtT(&c2b[1][0], a1 + 4); cvtT(&c2b[2][0], a1 + 8);
        float c3a[3][4], c3b[3][4];
        binit<3>(c3a, sbias + 72, qid);
        binit<3>(c3b, sbias + 72, qid);
        tstage2<3, 3>(a0, a1, TW + 27 * 32, lane, c3a, c3b);

        // ---- S4: [Y|Zv] K=32 -> oy ----
        u32 y0[16], y1[16];
        cvtT(Yf, y0);     cvtT(Yf + 4, y0 + 4);
        cvtT(&c3a[0][0], y0 + 8); cvtT(&c3a[1][0], y0 + 12);
        cvtT(Yf + 8, y1); cvtT(Yf + 12, y1 + 4);
        cvtT(&c3b[0][0], y1 + 8); cvtT(&c3b[1][0], y1 + 12);
        float c4a[3][4], c4b[3][4];
#pragma unroll
        for (int j = 0; j < 12; j++) { (&c4a[0][0])[j] = 0.0f; (&c4b[0][0])[j] = 0.0f; }
        tstage2<4, 3>(y0, y1, TW + 36 * 32, lane, c4a, c4b);

        // ---- lc ----
        {
            float ss0 = 0.0f, ss1 = 0.0f;
#pragma unroll
            for (int i = 0; i < 4; i++) {
                float dh0 = c4a[2][i] + c3a[2][i];
                float dh1 = c4b[2][i] + c3b[2][i];
                ss0 = fmaf(dh0, dh0, ss0);
                ss1 = fmaf(dh1, dh1, ss1);
            }
            lc = fmaf(wgt, ss0 + ss1, lc);
        }

        // ---- Y update (uses old X) ----
#pragma unroll
        for (int ttl = 0; ttl < 2; ttl++)
#pragma unroll
            for (int i = 0; i < 4; i++) {
                int k = ttl * 4 + i;
                float d0 = (i < 2) ? dlo0 : dhi0;
                float d1 = (i < 2) ? dlo1 : dhi1;
                Yf[k]     = fmaf(d0, c3a[ttl][i], fmaf(-(c4a[ttl][i] + Xf[k]), DT_F, Yf[k]));
                Yf[8 + k] = fmaf(d1, c3b[ttl][i], fmaf(-(c4b[ttl][i] + Xf[8 + k]), DT_F, Yf[8 + k]));
            }

        // ---- S5: [X|u] K=24 -> drift (tiles 0,1) | diff (tiles 2,3) ----
        u32 s0[12], s1[12];
#pragma unroll
        for (int i = 0; i < 8; i++) { s0[i] = xa0[i]; s1[i] = xa1[i]; }
        cvtT(&c3a[2][0], s0 + 8);
        cvtT(&c3b[2][0], s1 + 8);
        float c5a[4][4], c5b[4][4];
#pragma unroll
        for (int j = 0; j < 8; j++)  { (&c5a[0][0])[j] = GAMMA_F; (&c5b[0][0])[j] = GAMMA_F; }
#pragma unroll
        for (int j = 8; j < 16; j++) { (&c5a[0][0])[j] = SIGMA_F; (&c5b[0][0])[j] = SIGMA_F; }
        tstage2<3, 4>(s0, s1, TW + 48 * 32, lane, c5a, c5b);

        // ---- X update ----
#pragma unroll
        for (int ttl = 0; ttl < 2; ttl++)
#pragma unroll
            for (int i = 0; i < 4; i++) {
                int k = ttl * 4 + i;
                float d0 = (i < 2) ? dlo0 : dhi0;
                float d1 = (i < 2) ? dlo1 : dhi1;
                Xf[k]     = fmaf(d0, c5a[2 + ttl][i], fmaf(c5a[ttl][i], DT_F, Xf[k]));
                Xf[8 + k] = fmaf(d1, c5b[2 + ttl][i], fmaf(c5b[ttl][i], DT_F, Xf[8 + k]));
            }
    }

    float lb = 0.0f;
#pragma unroll
    for (int k = 0; k < 16; k++) {
        float d = Yf[k] - Xf[k];
        lb = fmaf(d, d, lb);
    }

    // ---- block reduction (4 warps) ----
#pragma unroll
    for (int off = 16; off; off >>= 1) {
        lb += __shfl_down_sync(0xffffffffu, lb, off);
        lc += __shfl_down_sync(0xffffffffu, lc, off);
    }
    if (lane == 0) { r0s[wid] = lb; r1s[wid] = lc; }
    __syncthreads();
    if (tid == 0) {
        g_p0[blockIdx.x] = (r0s[0] + r0s[1]) + (r0s[2] + r0s[3]);
        g_p1[blockIdx.x] = (r1s[0] + r1s[1]) + (r1s[2] + r1s[3]);
    }
}

// ---------------------------------------------------------------------------
// final reduction: NCTA (=256) partials -> 2 means
// ---------------------------------------------------------------------------
__global__ void __launch_bounds__(NCTA) finalize_kernel(float* __restrict__ out) {
    int tid = threadIdx.x;
    float a = g_p0[tid];
    float c = g_p1[tid];
#pragma unroll
    for (int o = 16; o; o >>= 1) {
        a += __shfl_down_sync(0xffffffffu, a, o);
        c += __shfl_down_sync(0xffffffffu, c, o);
    }
    __shared__ float sa[NCTA / 32], sc[NCTA / 32];
    int warp = tid >> 5, lane = tid & 31;
    if (lane == 0) { sa[warp] = a; sc[warp] = c; }
    __syncthreads();
    if (warp == 0) {
        a = (lane < NCTA / 32) ? sa[lane] : 0.0f;
        c = (lane < NCTA / 32) ? sc[lane] : 0.0f;
#pragma unroll
        for (int o = 4; o; o >>= 1) {
            a += __shfl_down_sync(0xffffffffu, a, o);
            c += __shfl_down_sync(0xffffffffu, c, o);
        }
        if (lane == 0) {
            out[0] = a * (1.0f / (float)BATCH);
            out[1] = c * (1.0f / (float)BATCH);
        }
    }
}

extern "C" void kernel_launch(void* const* d_in, const int* in_sizes, int n_in,
                              void* d_out, int out_size) {
    const float* dw  = (const float*)d_in[0];
    const float* X0  = (const float*)d_in[1];
    const float* A   = (const float*)d_in[2];
    const float* Bm  = (const float*)d_in[3];
    const float* Cm  = (const float*)d_in[4];
    const float* Dm  = (const float*)d_in[5];
    const float* pW1 = (const float*)d_in[6];
    const float* pb1 = (const float*)d_in[7];
    const float* pW2 = (const float*)d_in[8];
    const float* pb2 = (const float*)d_in[9];
    const float* pW3 = (const float*)d_in[10];
    const float* pb3 = (const float*)d_in[11];
    const float* zW1 = (const float*)d_in[12];
    const float* zb1 = (const float*)d_in[13];
    const float* zW2 = (const float*)d_in[14];
    const float* zb2 = (const float*)d_in[15];
    const float* zW3 = (const float*)d_in[16];
    const float* zb3 = (const float*)d_in[17];
    const float* yW1 = (const float*)d_in[18];
    const float* yb1 = (const float*)d_in[19];
    const float* yW2 = (const float*)d_in[20];
    const float* yb2 = (const float*)d_in[21];
    const float* yW3 = (const float*)d_in[22];
    const float* yb3 = (const float*)d_in[23];

    sim_kernel<<<NCTA, CTA_THREADS>>>(dw, X0, A, Bm, Cm, Dm,
                                      pW1, pb1, pW2, pb2, pW3, pb3,
                                      zW1, zb1, zW2, zb2, zW3, zb3,
                                      yW1, yb1, yW2, yb2, yW3, yb3);
    finalize_kernel<<<1, NCTA>>>((float*)d_out);
}